// round 13
// baseline (speedup 1.0000x reference)
#include <cuda_runtime.h>
#include <cuda_bf16.h>
#include <math.h>
#include <stdint.h>

#define BB   32
#define NPTS 577
#define DD   384
#define HH   1536
#define LL   12
#define KPAD 640

// ---------------- scratch (device globals; no allocs) ----------------
__device__ __align__(256) float g_x  [BB * NPTS * DD];
__device__ __align__(256) __nv_bfloat16 b_xn  [BB * NPTS * DD];
__device__ __align__(256) __nv_bfloat16 b_q   [BB * NPTS * DD];
__device__ __align__(256) __nv_bfloat16 b_qraw[BB * NPTS * DD];
__device__ __align__(256) __nv_bfloat16 b_k   [BB * KPAD * DD];
__device__ __align__(256) __nv_bfloat16 b_kraw[BB * KPAD * DD];
__device__ __align__(256) __nv_bfloat16 b_mem [BB * KPAD * DD];
__device__ __align__(256) __nv_bfloat16 b_vt  [BB * DD * KPAD];
__device__ __align__(256) __nv_bfloat16 b_attn[BB * NPTS * KPAD];
__device__ __align__(256) __nv_bfloat16 b_avraw[BB * NPTS * DD];
__device__ __align__(256) __nv_bfloat16 b_tmp [BB * NPTS * DD];
__device__ __align__(256) __nv_bfloat16 b_h   [BB * NPTS * HH];
__device__ __align__(256) __nv_bfloat16 w_qkv [LL * 3 * DD * DD];
__device__ __align__(256) __nv_bfloat16 w_proj[LL * DD * DD];
__device__ __align__(256) __nv_bfloat16 w_fc1 [LL * HH * DD];
__device__ __align__(256) __nv_bfloat16 w_fc2 [LL * DD * HH];

// ---------------- PTX helpers (base ISA only) ----------------
__device__ __forceinline__ void cpa16(uint32_t s, const void* g) {
    asm volatile("cp.async.cg.shared.global [%0], [%1], 16;" :: "r"(s), "l"(g));
}
__device__ __forceinline__ void cpa_commit() {
    asm volatile("cp.async.commit_group;" ::: "memory");
}
__device__ __forceinline__ void ldm4(uint32_t* r, uint32_t addr) {
    asm volatile("ldmatrix.sync.aligned.m8n8.x4.shared.b16 {%0,%1,%2,%3}, [%4];"
        : "=r"(r[0]), "=r"(r[1]), "=r"(r[2]), "=r"(r[3]) : "r"(addr));
}
__device__ __forceinline__ void ldm2(uint32_t* r, uint32_t addr) {
    asm volatile("ldmatrix.sync.aligned.m8n8.x2.shared.b16 {%0,%1}, [%2];"
        : "=r"(r[0]), "=r"(r[1]) : "r"(addr));
}
__device__ __forceinline__ void mma16816(float* c, const uint32_t* a, const uint32_t* b) {
    asm volatile("mma.sync.aligned.m16n8k16.row.col.f32.bf16.bf16.f32 "
        "{%0,%1,%2,%3}, {%4,%5,%6,%7}, {%8,%9}, {%0,%1,%2,%3};"
        : "+f"(c[0]), "+f"(c[1]), "+f"(c[2]), "+f"(c[3])
        : "r"(a[0]), "r"(a[1]), "r"(a[2]), "r"(a[3]), "r"(b[0]), "r"(b[1]));
}

// ---------------- elementwise kernels ----------------
__global__ void f2bf(const float* __restrict__ in, __nv_bfloat16* __restrict__ out, int n) {
    int i = (blockIdx.x * 256 + threadIdx.x) * 4;
    if (i >= n) return;
    float4 v = *(const float4*)(in + i);
    __nv_bfloat162 p0 = __floats2bfloat162_rn(v.x, v.y);
    __nv_bfloat162 p1 = __floats2bfloat162_rn(v.z, v.w);
    *(uint2*)(out + i) = make_uint2(*(uint32_t*)&p0, *(uint32_t*)&p1);
}

__global__ void build_x_mem(const float* __restrict__ inp, float* __restrict__ x,
                            __nv_bfloat16* __restrict__ mem, int r) {
    int d = threadIdx.x, n = blockIdx.x, b = blockIdx.y;
    long xi = ((long)b * NPTS + n) * DD + d;
    long mi = ((long)b * KPAD + n) * DD + d;
    if (n == 0) {
        float val = (r == 0) ? inp[xi] : x[xi];
        x[xi] = val;
        __nv_bfloat16 bv = __float2bfloat16(val);
        mem[mi] = bv;
        mem[((long)b * KPAD + NPTS + r) * DD + d] = bv;
    } else {
        float val = inp[xi];
        x[xi] = val;
        mem[mi] = __float2bfloat16(val);
    }
}

// warp-per-row LN, fp32 in -> bf16 out
__global__ void ln_f32(const float* __restrict__ in, const float* __restrict__ w,
                       const float* __restrict__ b, __nv_bfloat16* __restrict__ out,
                       int rows, long strIn, long strOut, float scale) {
    int warp = threadIdx.x >> 5, lane = threadIdx.x & 31;
    int row = blockIdx.x * 8 + warp;
    if (row >= rows) return;
    const float* x = in + (long)blockIdx.y * strIn + (long)row * DD;
    __nv_bfloat16* y = out + (long)blockIdx.y * strOut + (long)row * DD;
    float4 v[3]; float s = 0.f;
    #pragma unroll
    for (int j = 0; j < 3; j++) {
        v[j] = *(const float4*)(x + lane * 4 + j * 128);
        s += (v[j].x + v[j].y) + (v[j].z + v[j].w);
    }
    #pragma unroll
    for (int o = 16; o; o >>= 1) s += __shfl_xor_sync(~0u, s, o);
    float mu = s * (1.f / 384.f), q = 0.f;
    #pragma unroll
    for (int j = 0; j < 3; j++) {
        v[j].x -= mu; v[j].y -= mu; v[j].z -= mu; v[j].w -= mu;
        q += v[j].x * v[j].x + v[j].y * v[j].y + v[j].z * v[j].z + v[j].w * v[j].w;
    }
    #pragma unroll
    for (int o = 16; o; o >>= 1) q += __shfl_xor_sync(~0u, q, o);
    float rs = rsqrtf(q * (1.f / 384.f) + 1e-6f);
    #pragma unroll
    for (int j = 0; j < 3; j++) {
        int c = lane * 4 + j * 128;
        float4 wv = *(const float4*)(w + c);
        float4 bv = *(const float4*)(b + c);
        __nv_bfloat162 p0 = __floats2bfloat162_rn((v[j].x * rs * wv.x + bv.x) * scale,
                                                  (v[j].y * rs * wv.y + bv.y) * scale);
        __nv_bfloat162 p1 = __floats2bfloat162_rn((v[j].z * rs * wv.z + bv.z) * scale,
                                                  (v[j].w * rs * wv.w + bv.w) * scale);
        *(uint2*)(y + c) = make_uint2(*(uint32_t*)&p0, *(uint32_t*)&p1);
    }
}

// warp-per-row LN, bf16 in -> bf16 out
__global__ void ln_b16(const __nv_bfloat16* __restrict__ in, const float* __restrict__ w,
                       const float* __restrict__ b, __nv_bfloat16* __restrict__ out,
                       int rows, long strIn, long strOut, float scale) {
    int warp = threadIdx.x >> 5, lane = threadIdx.x & 31;
    int row = blockIdx.x * 8 + warp;
    if (row >= rows) return;
    const __nv_bfloat16* x = in + (long)blockIdx.y * strIn + (long)row * DD;
    __nv_bfloat16* y = out + (long)blockIdx.y * strOut + (long)row * DD;
    float4 v[3]; float s = 0.f;
    #pragma unroll
    for (int j = 0; j < 3; j++) {
        uint2 u = *(const uint2*)(x + lane * 4 + j * 128);
        __nv_bfloat162 h0 = *(__nv_bfloat162*)&u.x;
        __nv_bfloat162 h1 = *(__nv_bfloat162*)&u.y;
        v[j].x = __bfloat162float(h0.x); v[j].y = __bfloat162float(h0.y);
        v[j].z = __bfloat162float(h1.x); v[j].w = __bfloat162float(h1.y);
        s += (v[j].x + v[j].y) + (v[j].z + v[j].w);
    }
    #pragma unroll
    for (int o = 16; o; o >>= 1) s += __shfl_xor_sync(~0u, s, o);
    float mu = s * (1.f / 384.f), q = 0.f;
    #pragma unroll
    for (int j = 0; j < 3; j++) {
        v[j].x -= mu; v[j].y -= mu; v[j].z -= mu; v[j].w -= mu;
        q += v[j].x * v[j].x + v[j].y * v[j].y + v[j].z * v[j].z + v[j].w * v[j].w;
    }
    #pragma unroll
    for (int o = 16; o; o >>= 1) q += __shfl_xor_sync(~0u, q, o);
    float rs = rsqrtf(q * (1.f / 384.f) + 1e-6f);
    #pragma unroll
    for (int j = 0; j < 3; j++) {
        int c = lane * 4 + j * 128;
        float4 wv = *(const float4*)(w + c);
        float4 bv = *(const float4*)(b + c);
        __nv_bfloat162 p0 = __floats2bfloat162_rn((v[j].x * rs * wv.x + bv.x) * scale,
                                                  (v[j].y * rs * wv.y + bv.y) * scale);
        __nv_bfloat162 p1 = __floats2bfloat162_rn((v[j].z * rs * wv.z + bv.z) * scale,
                                                  (v[j].w * rs * wv.w + bv.w) * scale);
        *(uint2*)(y + c) = make_uint2(*(uint32_t*)&p0, *(uint32_t*)&p1);
    }
}

// ---------------- GEMM config ----------------
#define SROWB 80
#define NSTAGE 3

#define EPI_QB    0
#define EPI_KV    1
#define EPI_EXP   2
#define EPI_AVB   3
#define EPI_GELU  4
#define EPI_RES   5

// =========== small: BM=128, BN=128, 256 thr (batched attention GEMMs) ===========
#define BM 128
#define BN 128
#define STGB ((BM + BN) * SROWB)   // 20480
#define SMEMB (NSTAGE * STGB)      // 61440

template<int EPI>
__global__ void __launch_bounds__(256, 2)
mma_gemm(const __nv_bfloat16* __restrict__ A, const __nv_bfloat16* __restrict__ B,
         const float* __restrict__ bias, const float* __restrict__ ls,
         void* __restrict__ Cv, void* __restrict__ Cv2,
         int M, int K, int lda, int ldb, int ldc, int curM,
         long strA, long strB, long strC, long strC2)
{
    extern __shared__ __align__(16) char smem_[];
    __shared__ float rinv[BM];
    A += (long)blockIdx.z * strA;
    B += (long)blockIdx.z * strB;
    int m0 = blockIdx.y * BM, n0 = blockIdx.x * BN;
    int t = threadIdx.x;
    int warp = t >> 5, lane = t & 31;
    int wm = warp & 1, wn = warp >> 1;

    float acc[4][4][4];
    #pragma unroll
    for (int i = 0; i < 4; i++)
        #pragma unroll
        for (int j = 0; j < 4; j++)
            #pragma unroll
            for (int q = 0; q < 4; q++) acc[i][j][q] = 0.f;

    uint32_t sb = (uint32_t)__cvta_generic_to_shared(smem_);
    int sRow = t >> 2, sCol = (t & 3) * 16;
    auto stage = [&](int kt) {
        uint32_t tA = sb + (uint32_t)((kt % NSTAGE) * STGB);
        uint32_t tB = tA + BM * SROWB;
        int k0 = kt * 32;
        #pragma unroll
        for (int i2 = 0; i2 < 2; i2++) {
            int row = sRow + i2 * 64;
            int gm = m0 + row; gm = gm < M ? gm : M - 1;
            cpa16(tA + (uint32_t)(row * SROWB + sCol), A + (long)gm * lda + k0 + sCol / 2);
        }
        #pragma unroll
        for (int i2 = 0; i2 < 2; i2++) {
            int row = sRow + i2 * 64;
            cpa16(tB + (uint32_t)(row * SROWB + sCol), B + (long)(n0 + row) * ldb + k0 + sCol / 2);
        }
        cpa_commit();
    };

    const int T = K >> 5;
    stage(0); stage(1);

    uint32_t aOff = (uint32_t)((wm * 64 + (lane & 15)) * SROWB + (lane >> 4) * 16);
    uint32_t bOff = (uint32_t)(BM * SROWB + (wn * 32 + (lane & 7)) * SROWB + ((lane >> 3) & 1) * 16);

    float psum = 0.f;

    for (int i = 0; i < T; i++) {
        asm volatile("cp.async.wait_group 1;" ::: "memory");
        __syncthreads();
        if (EPI == EPI_AVB) {
            const __nv_bfloat16* arow = (const __nv_bfloat16*)
                (smem_ + (size_t)(i % NSTAGE) * STGB + (t >> 1) * SROWB + (t & 1) * 32);
            #pragma unroll
            for (int z = 0; z < 4; z++) {
                uint2 u = *(const uint2*)(arow + z * 4);
                __nv_bfloat162 a0 = *(__nv_bfloat162*)&u.x;
                __nv_bfloat162 a1 = *(__nv_bfloat162*)&u.y;
                psum += (__bfloat162float(a0.x) + __bfloat162float(a0.y))
                      + (__bfloat162float(a1.x) + __bfloat162float(a1.y));
            }
        }
        if (i + 2 < T) stage(i + 2);        // single-sync: stage before compute
        else cpa_commit();
        uint32_t tbase = sb + (uint32_t)((i % NSTAGE) * STGB);
        #pragma unroll
        for (int kk = 0; kk < 2; kk++) {
            uint32_t af[4][4], bf_[4][2];
            #pragma unroll
            for (int mt = 0; mt < 4; mt++)
                ldm4(af[mt], tbase + aOff + (uint32_t)(mt * 16 * SROWB + kk * 32));
            #pragma unroll
            for (int nt = 0; nt < 4; nt++)
                ldm2(bf_[nt], tbase + bOff + (uint32_t)(nt * 8 * SROWB + kk * 32));
            #pragma unroll
            for (int mt = 0; mt < 4; mt++)
                #pragma unroll
                for (int nt = 0; nt < 4; nt++)
                    mma16816(acc[mt][nt], af[mt], bf_[nt]);
        }
    }
    __syncthreads();

    if (EPI == EPI_AVB) {
        psum += __shfl_xor_sync(~0u, psum, 1);
        if ((t & 1) == 0) rinv[t >> 1] = 1.f / psum;
        __syncthreads();
    }

    int g = lane >> 2, tg = lane & 3;
    #pragma unroll
    for (int mt = 0; mt < 4; mt++) {
        #pragma unroll
        for (int nt = 0; nt < 4; nt++) {
            int gm = m0 + wm * 64 + mt * 16 + g;
            int gn = n0 + wn * 32 + nt * 8 + tg * 2;
            float* cc = acc[mt][nt];
            float b0 = 0.f, b1 = 0.f;
            if (EPI == EPI_KV) {
                float2 bv = *(const float2*)&bias[gn]; b0 = bv.x; b1 = bv.y;
            }
            #pragma unroll
            for (int h = 0; h < 2; h++) {
                int gmh = gm + h * 8;
                if (gmh >= M) continue;
                float v0 = cc[h * 2 + 0], v1 = cc[h * 2 + 1];
                if (EPI == EPI_KV) {
                    if (gn < DD) {
                        __nv_bfloat16* C = (__nv_bfloat16*)Cv + (long)blockIdx.z * strC;
                        __nv_bfloat162 p = __floats2bfloat162_rn(v0 + b0, v1 + b1);
                        *(uint32_t*)&C[(long)gmh * ldc + gn] = *(uint32_t*)&p;
                    } else {
                        __nv_bfloat16* C2 = (__nv_bfloat16*)Cv2 + (long)blockIdx.z * strC2;
                        int vn = gn - DD;
                        C2[(long)vn * KPAD + gmh]       = __float2bfloat16(v0 + b0);
                        C2[(long)(vn + 1) * KPAD + gmh] = __float2bfloat16(v1 + b1);
                    }
                } else if (EPI == EPI_EXP) {
                    __nv_bfloat16* C = (__nv_bfloat16*)Cv + (long)blockIdx.z * strC;
                    float e0 = (gn < curM)     ? __expf(v0) : 0.f;
                    float e1 = (gn + 1 < curM) ? __expf(v1) : 0.f;
                    __nv_bfloat162 p = __floats2bfloat162_rn(e0, e1);
                    *(uint32_t*)&C[(long)gmh * ldc + gn] = *(uint32_t*)&p;
                } else if (EPI == EPI_AVB) {
                    __nv_bfloat16* C = (__nv_bfloat16*)Cv + (long)blockIdx.z * strC;
                    float inv = rinv[gmh - m0];
                    __nv_bfloat162 p = __floats2bfloat162_rn(v0 * inv, v1 * inv);
                    *(uint32_t*)&C[(long)gmh * ldc + gn] = *(uint32_t*)&p;
                }
            }
        }
    }
}

// =========== big: BM=256, BN=128, 512 thr (flat GEMMs: q / proj / fc1 / fc2) ===========
#define GBM 256
#define GBN 128
#define GSTGB ((GBM + GBN) * SROWB)   // 30720
#define GSMEMB (NSTAGE * GSTGB)       // 92160

template<int EPI>
__global__ void __launch_bounds__(512, 1)
mma_big(const __nv_bfloat16* __restrict__ A, const __nv_bfloat16* __restrict__ B,
        const float* __restrict__ bias, const float* __restrict__ ls,
        void* __restrict__ Cv,
        int M, int K, int lda, int ldb, int ldc)
{
    extern __shared__ __align__(16) char smem_[];
    int m0 = blockIdx.y * GBM, n0 = blockIdx.x * GBN;
    int t = threadIdx.x;
    int warp = t >> 5, lane = t & 31;
    int wm = warp & 3, wn = warp >> 2;

    float acc[4][4][4];
    #pragma unroll
    for (int i = 0; i < 4; i++)
        #pragma unroll
        for (int j = 0; j < 4; j++)
            #pragma unroll
            for (int q = 0; q < 4; q++) acc[i][j][q] = 0.f;

    uint32_t sb = (uint32_t)__cvta_generic_to_shared(smem_);
    int sRow = t >> 2, sCol = (t & 3) * 16;     // sRow 0..127
    auto stage = [&](int kt) {
        uint32_t tA = sb + (uint32_t)((kt % NSTAGE) * GSTGB);
        uint32_t tB = tA + GBM * SROWB;
        int k0 = kt * 32;
        #pragma unroll
        for (int i2 = 0; i2 < 2; i2++) {
            int row = sRow + i2 * 128;
            int gm = m0 + row; gm = gm < M ? gm : M - 1;
            cpa16(tA + (uint32_t)(row * SROWB + sCol), A + (long)gm * lda + k0 + sCol / 2);
        }
        cpa16(tB + (uint32_t)(sRow * SROWB + sCol), B + (long)(n0 + sRow) * ldb + k0 + sCol / 2);
        cpa_commit();
    };

    const int T = K >> 5;
    stage(0); stage(1);

    uint32_t aOff = (uint32_t)((wm * 64 + (lane & 15)) * SROWB + (lane >> 4) * 16);
    uint32_t bOff = (uint32_t)(GBM * SROWB + (wn * 32 + (lane & 7)) * SROWB + ((lane >> 3) & 1) * 16);

    for (int i = 0; i < T; i++) {
        asm volatile("cp.async.wait_group 1;" ::: "memory");
        __syncthreads();
        if (i + 2 < T) stage(i + 2);
        else cpa_commit();
        uint32_t tbase = sb + (uint32_t)((i % NSTAGE) * GSTGB);
        #pragma unroll
        for (int kk = 0; kk < 2; kk++) {
            uint32_t af[4][4], bf_[4][2];
            #pragma unroll
            for (int mt = 0; mt < 4; mt++)
                ldm4(af[mt], tbase + aOff + (uint32_t)(mt * 16 * SROWB + kk * 32));
            #pragma unroll
            for (int nt = 0; nt < 4; nt++)
                ldm2(bf_[nt], tbase + bOff + (uint32_t)(nt * 8 * SROWB + kk * 32));
            #pragma unroll
            for (int mt = 0; mt < 4; mt++)
                #pragma unroll
                for (int nt = 0; nt < 4; nt++)
                    mma16816(acc[mt][nt], af[mt], bf_[nt]);
        }
    }
    __syncthreads();

    int g = lane >> 2, tg = lane & 3;
    #pragma unroll
    for (int mt = 0; mt < 4; mt++) {
        #pragma unroll
        for (int nt = 0; nt < 4; nt++) {
            int gm = m0 + wm * 64 + mt * 16 + g;
            int gn = n0 + wn * 32 + nt * 8 + tg * 2;
            float* cc = acc[mt][nt];
            float2 bv = *(const float2*)&bias[gn];
            float b0 = bv.x, b1 = bv.y, l0 = 0.f, l1 = 0.f;
            if (EPI == EPI_RES) { float2 lv = *(const float2*)&ls[gn]; l0 = lv.x; l1 = lv.y; }
            #pragma unroll
            for (int h = 0; h < 2; h++) {
                int gmh = gm + h * 8;
                if (gmh >= M) continue;
                float v0 = cc[h * 2 + 0], v1 = cc[h * 2 + 1];
                if (EPI == EPI_QB) {
                    __nv_bfloat16* C = (__nv_bfloat16*)Cv;
                    __nv_bfloat162 p = __floats2bfloat162_rn(v0 + b0, v1 + b1);
                    *(uint32_t*)&C[(long)gmh * ldc + gn] = *(uint32_t*)&p;
                } else if (EPI == EPI_RES) {
                    float* C = (float*)Cv;
                    long ci = (long)gmh * ldc + gn;
                    float2 old = *(float2*)&C[ci];
                    *(float2*)&C[ci] = make_float2((v0 + b0) * l0 + old.x,
                                                   (v1 + b1) * l1 + old.y);
                } else {   // EPI_GELU
                    __nv_bfloat16* C = (__nv_bfloat16*)Cv;
                    v0 += b0; v1 += b1;
                    v0 = 0.5f * v0 * (1.f + erff(v0 * 0.70710678118654752f));
                    v1 = 0.5f * v1 * (1.f + erff(v1 * 0.70710678118654752f));
                    __nv_bfloat162 p = __floats2bfloat162_rn(v0, v1);
                    *(uint32_t*)&C[(long)gmh * ldc + gn] = *(uint32_t*)&p;
                }
            }
        }
    }
}

// ---------------- host ----------------
extern "C" void kernel_launch(void* const* d_in, const int* in_sizes, int n_in,
                              void* d_out, int out_size)
{
    const float* x_in = (const float*)d_in[0];
    const float* n1w = (const float*)d_in[1];  const float* n1b = (const float*)d_in[2];
    const float* qkvw = (const float*)d_in[3]; const float* qkvb = (const float*)d_in[4];
    const float* qnw = (const float*)d_in[5];  const float* qnb = (const float*)d_in[6];
    const float* knw = (const float*)d_in[7];  const float* knb = (const float*)d_in[8];
    const float* anw = (const float*)d_in[9];  const float* anb = (const float*)d_in[10];
    const float* projw = (const float*)d_in[11]; const float* projb = (const float*)d_in[12];
    const float* ls1 = (const float*)d_in[13];
    const float* n2w = (const float*)d_in[14]; const float* n2b = (const float*)d_in[15];
    const float* fc1w = (const float*)d_in[16]; const float* fc1b = (const float*)d_in[17];
    const float* fc2w = (const float*)d_in[18]; const float* fc2b = (const float*)d_in[19];
    const float* ls2 = (const float*)d_in[20];

    float *gx;
    __nv_bfloat16 *bxn, *bq, *bqr, *bk, *bkr, *bmem, *bvt, *battn, *bavr, *btmp, *bh;
    __nv_bfloat16 *wq, *wp, *w1, *w2;
    cudaGetSymbolAddress((void**)&gx, g_x);
    cudaGetSymbolAddress((void**)&bxn, b_xn);   cudaGetSymbolAddress((void**)&bq, b_q);
    cudaGetSymbolAddress((void**)&bqr, b_qraw); cudaGetSymbolAddress((void**)&bk, b_k);
    cudaGetSymbolAddress((void**)&bkr, b_kraw); cudaGetSymbolAddress((void**)&bmem, b_mem);
    cudaGetSymbolAddress((void**)&bvt, b_vt);   cudaGetSymbolAddress((void**)&battn, b_attn);
    cudaGetSymbolAddress((void**)&bavr, b_avraw);cudaGetSymbolAddress((void**)&btmp, b_tmp);
    cudaGetSymbolAddress((void**)&bh, b_h);
    cudaGetSymbolAddress((void**)&wq, w_qkv);   cudaGetSymbolAddress((void**)&wp, w_proj);
    cudaGetSymbolAddress((void**)&w1, w_fc1);   cudaGetSymbolAddress((void**)&w2, w_fc2);

    cudaFuncSetAttribute(mma_gemm<EPI_KV>,  cudaFuncAttributeMaxDynamicSharedMemorySize, SMEMB);
    cudaFuncSetAttribute(mma_gemm<EPI_EXP>, cudaFuncAttributeMaxDynamicSharedMemorySize, SMEMB);
    cudaFuncSetAttribute(mma_gemm<EPI_AVB>, cudaFuncAttributeMaxDynamicSharedMemorySize, SMEMB);
    cudaFuncSetAttribute(mma_big<EPI_QB>,   cudaFuncAttributeMaxDynamicSharedMemorySize, GSMEMB);
    cudaFuncSetAttribute(mma_big<EPI_GELU>, cudaFuncAttributeMaxDynamicSharedMemorySize, GSMEMB);
    cudaFuncSetAttribute(mma_big<EPI_RES>,  cudaFuncAttributeMaxDynamicSharedMemorySize, GSMEMB);

    int n;
    n = LL * 3 * DD * DD; f2bf<<<(n / 4 + 255) / 256, 256>>>(qkvw, wq, n);
    n = LL * DD * DD;     f2bf<<<(n / 4 + 255) / 256, 256>>>(projw, wp, n);
    n = LL * HH * DD;     f2bf<<<(n / 4 + 255) / 256, 256>>>(fc1w, w1, n);
    n = LL * DD * HH;     f2bf<<<(n / 4 + 255) / 256, 256>>>(fc2w, w2, n);

    const float scale = 1.0f / sqrtf((float)DD);
    const long xS = (long)NPTS * DD, mS = (long)KPAD * DD;
    const long vtS = (long)DD * KPAD, aS = (long)NPTS * KPAD;
    const int Mflat = BB * NPTS;                 // 18464
    const int KAV = 608;
    const int MBIG = (Mflat + GBM - 1) / GBM;    // 73
    const dim3 gFlatD(3, MBIG, 1), gFlatH(12, MBIG, 1);

    for (int r = 0; r < 4; r++) {
        int curM = NPTS + r;
        build_x_mem<<<dim3(NPTS, BB), DD>>>(x_in, gx, bmem, r);
        for (int l = 0; l < LL; l++) {
            const __nv_bfloat16* Wq = wq + (long)l * 3 * DD * DD;
            const __nv_bfloat16* Wkv = Wq + (long)DD * DD;
            const float* bqp = qkvb + (long)l * 3 * DD;
            const float* bkvp = bqp + DD;

            // xn = LN(x, norm1) -> bf16
            ln_f32<<<(Mflat + 7) / 8, 256>>>(gx, n1w + l * DD, n1b + l * DD, bxn,
                Mflat, 0, 0, 1.f);
            // q = xn @ Wq^T + bq -> bf16 ; q-LN (scale folded) -> bf16
            mma_big<EPI_QB><<<gFlatD, 512, GSMEMB>>>(bxn, Wq, bqp, nullptr, bqr,
                Mflat, DD, DD, DD, DD);
            ln_b16<<<(Mflat + 7) / 8, 256>>>(bqr, qnw + l * DD, qnb + l * DD, bq,
                Mflat, 0, 0, scale);
            // fused K+V: [k | v] = mem @ [Wk;Wv]^T + [bk;bv]
            dim3 gKV(6, 5, BB);
            mma_gemm<EPI_KV><<<gKV, 256, SMEMB>>>(bmem, Wkv, bkvp, nullptr, bkr, bvt,
                curM, DD, DD, DD, DD, 0, mS, 0, mS, vtS);
            ln_b16<<<dim3((curM + 7) / 8, 1, BB), 256>>>(bkr, knw + l * DD, knb + l * DD, bk,
                curM, mS, mS, 1.f);
            // probs = exp(q_scaled @ k^T), masked -> bf16 (unnormalized)
            dim3 gLog(5, 5, BB);
            mma_gemm<EPI_EXP><<<gLog, 256, SMEMB>>>(bq, bk, nullptr, nullptr, battn, nullptr,
                NPTS, DD, DD, DD, KPAD, curM, xS, mS, aS, 0);
            // prod = (probs @ vT^T) / rowsum(probs) -> bf16
            dim3 gProd(3, 5, BB);
            mma_gemm<EPI_AVB><<<gProd, 256, SMEMB>>>(battn, bvt, nullptr, nullptr, bavr, nullptr,
                NPTS, KAV, KPAD, KPAD, DD, 0, aS, vtS, xS, 0);
            // an-LN -> bf16
            ln_b16<<<dim3((NPTS + 7) / 8, 1, BB), 256>>>(bavr, anw + l * DD, anb + l * DD, btmp,
                NPTS, xS, xS, 1.f);
            // x += (prodn @ proj^T + pb) * ls1
            mma_big<EPI_RES><<<gFlatD, 512, GSMEMB>>>(btmp, wp + (long)l * DD * DD,
                projb + l * DD, ls1 + l * DD, gx, Mflat, DD, DD, DD, DD);
            // norm2 -> bf16
            ln_f32<<<(Mflat + 7) / 8, 256>>>(gx, n2w + l * DD, n2b + l * DD, bxn,
                Mflat, 0, 0, 1.f);
            // h = gelu(xn @ fc1^T + b1) -> bf16
            mma_big<EPI_GELU><<<gFlatH, 512, GSMEMB>>>(bxn, w1 + (long)l * HH * DD,
                fc1b + (long)l * HH, nullptr, bh, Mflat, DD, DD, DD, HH);
            // x += (h @ fc2^T + b2) * ls2
            mma_big<EPI_RES><<<gFlatD, 512, GSMEMB>>>(bh, w2 + (long)l * DD * HH,
                fc2b + l * DD, ls2 + l * DD, gx, Mflat, HH, HH, HH, DD);
        }
    }
    cudaMemcpyAsync(d_out, gx, (size_t)BB * NPTS * DD * sizeof(float),
                    cudaMemcpyDeviceToDevice);
}

// round 14
// speedup vs baseline: 1.1655x; 1.1655x over previous
#include <cuda_runtime.h>
#include <cuda_bf16.h>
#include <math.h>
#include <stdint.h>

#define BB   32
#define NPTS 577
#define DD   384
#define HH   1536
#define LL   12
#define KPAD 640

// ---------------- scratch (device globals; no allocs) ----------------
__device__ __align__(256) float g_x  [BB * NPTS * DD];
__device__ __align__(256) __nv_bfloat16 b_xn  [BB * NPTS * DD];
__device__ __align__(256) __nv_bfloat16 b_q   [BB * NPTS * DD];
__device__ __align__(256) __nv_bfloat16 b_qraw[BB * NPTS * DD];
__device__ __align__(256) __nv_bfloat16 b_k   [BB * KPAD * DD];
__device__ __align__(256) __nv_bfloat16 b_kraw[BB * KPAD * DD];
__device__ __align__(256) __nv_bfloat16 b_mem [BB * KPAD * DD];
__device__ __align__(256) __nv_bfloat16 b_vt  [BB * DD * KPAD];
__device__ __align__(256) __nv_bfloat16 b_attn[BB * NPTS * KPAD];
__device__ __align__(256) __nv_bfloat16 b_avraw[BB * NPTS * DD];
__device__ __align__(256) __nv_bfloat16 b_tmp [BB * NPTS * DD];
__device__ __align__(256) __nv_bfloat16 b_h   [BB * NPTS * HH];
__device__ __align__(256) __nv_bfloat16 w_qkv [LL * 3 * DD * DD];
__device__ __align__(256) __nv_bfloat16 w_proj[LL * DD * DD];
__device__ __align__(256) __nv_bfloat16 w_fc1 [LL * HH * DD];
__device__ __align__(256) __nv_bfloat16 w_fc2 [LL * DD * HH];

// ---------------- PTX helpers (base ISA only) ----------------
__device__ __forceinline__ void cpa16(uint32_t s, const void* g) {
    asm volatile("cp.async.cg.shared.global [%0], [%1], 16;" :: "r"(s), "l"(g));
}
__device__ __forceinline__ void cpa_commit() {
    asm volatile("cp.async.commit_group;" ::: "memory");
}
__device__ __forceinline__ void ldm4(uint32_t* r, uint32_t addr) {
    asm volatile("ldmatrix.sync.aligned.m8n8.x4.shared.b16 {%0,%1,%2,%3}, [%4];"
        : "=r"(r[0]), "=r"(r[1]), "=r"(r[2]), "=r"(r[3]) : "r"(addr));
}
__device__ __forceinline__ void ldm2(uint32_t* r, uint32_t addr) {
    asm volatile("ldmatrix.sync.aligned.m8n8.x2.shared.b16 {%0,%1}, [%2];"
        : "=r"(r[0]), "=r"(r[1]) : "r"(addr));
}
__device__ __forceinline__ void mma16816(float* c, const uint32_t* a, const uint32_t* b) {
    asm volatile("mma.sync.aligned.m16n8k16.row.col.f32.bf16.bf16.f32 "
        "{%0,%1,%2,%3}, {%4,%5,%6,%7}, {%8,%9}, {%0,%1,%2,%3};"
        : "+f"(c[0]), "+f"(c[1]), "+f"(c[2]), "+f"(c[3])
        : "r"(a[0]), "r"(a[1]), "r"(a[2]), "r"(a[3]), "r"(b[0]), "r"(b[1]));
}

// ---------------- elementwise kernels ----------------
__global__ void f2bf(const float* __restrict__ in, __nv_bfloat16* __restrict__ out, int n) {
    int i = (blockIdx.x * 256 + threadIdx.x) * 4;
    if (i >= n) return;
    float4 v = *(const float4*)(in + i);
    __nv_bfloat162 p0 = __floats2bfloat162_rn(v.x, v.y);
    __nv_bfloat162 p1 = __floats2bfloat162_rn(v.z, v.w);
    *(uint2*)(out + i) = make_uint2(*(uint32_t*)&p0, *(uint32_t*)&p1);
}

__global__ void build_x_mem(const float* __restrict__ inp, float* __restrict__ x,
                            __nv_bfloat16* __restrict__ mem, int r) {
    int d = threadIdx.x, n = blockIdx.x, b = blockIdx.y;
    long xi = ((long)b * NPTS + n) * DD + d;
    long mi = ((long)b * KPAD + n) * DD + d;
    if (n == 0) {
        float val = (r == 0) ? inp[xi] : x[xi];
        x[xi] = val;
        __nv_bfloat16 bv = __float2bfloat16(val);
        mem[mi] = bv;
        mem[((long)b * KPAD + NPTS + r) * DD + d] = bv;
    } else {
        float val = inp[xi];
        x[xi] = val;
        mem[mi] = __float2bfloat16(val);
    }
}

// warp-per-row LN, fp32 in -> bf16 out
__global__ void ln_f32(const float* __restrict__ in, const float* __restrict__ w,
                       const float* __restrict__ b, __nv_bfloat16* __restrict__ out,
                       int rows, long strIn, long strOut, float scale) {
    int warp = threadIdx.x >> 5, lane = threadIdx.x & 31;
    int row = blockIdx.x * 8 + warp;
    if (row >= rows) return;
    const float* x = in + (long)blockIdx.y * strIn + (long)row * DD;
    __nv_bfloat16* y = out + (long)blockIdx.y * strOut + (long)row * DD;
    float4 v[3]; float s = 0.f;
    #pragma unroll
    for (int j = 0; j < 3; j++) {
        v[j] = *(const float4*)(x + lane * 4 + j * 128);
        s += (v[j].x + v[j].y) + (v[j].z + v[j].w);
    }
    #pragma unroll
    for (int o = 16; o; o >>= 1) s += __shfl_xor_sync(~0u, s, o);
    float mu = s * (1.f / 384.f), q = 0.f;
    #pragma unroll
    for (int j = 0; j < 3; j++) {
        v[j].x -= mu; v[j].y -= mu; v[j].z -= mu; v[j].w -= mu;
        q += v[j].x * v[j].x + v[j].y * v[j].y + v[j].z * v[j].z + v[j].w * v[j].w;
    }
    #pragma unroll
    for (int o = 16; o; o >>= 1) q += __shfl_xor_sync(~0u, q, o);
    float rs = rsqrtf(q * (1.f / 384.f) + 1e-6f);
    #pragma unroll
    for (int j = 0; j < 3; j++) {
        int c = lane * 4 + j * 128;
        float4 wv = *(const float4*)(w + c);
        float4 bv = *(const float4*)(b + c);
        __nv_bfloat162 p0 = __floats2bfloat162_rn((v[j].x * rs * wv.x + bv.x) * scale,
                                                  (v[j].y * rs * wv.y + bv.y) * scale);
        __nv_bfloat162 p1 = __floats2bfloat162_rn((v[j].z * rs * wv.z + bv.z) * scale,
                                                  (v[j].w * rs * wv.w + bv.w) * scale);
        *(uint2*)(y + c) = make_uint2(*(uint32_t*)&p0, *(uint32_t*)&p1);
    }
}

// warp-per-row LN, bf16 in -> bf16 out
__global__ void ln_b16(const __nv_bfloat16* __restrict__ in, const float* __restrict__ w,
                       const float* __restrict__ b, __nv_bfloat16* __restrict__ out,
                       int rows, long strIn, long strOut, float scale) {
    int warp = threadIdx.x >> 5, lane = threadIdx.x & 31;
    int row = blockIdx.x * 8 + warp;
    if (row >= rows) return;
    const __nv_bfloat16* x = in + (long)blockIdx.y * strIn + (long)row * DD;
    __nv_bfloat16* y = out + (long)blockIdx.y * strOut + (long)row * DD;
    float4 v[3]; float s = 0.f;
    #pragma unroll
    for (int j = 0; j < 3; j++) {
        uint2 u = *(const uint2*)(x + lane * 4 + j * 128);
        __nv_bfloat162 h0 = *(__nv_bfloat162*)&u.x;
        __nv_bfloat162 h1 = *(__nv_bfloat162*)&u.y;
        v[j].x = __bfloat162float(h0.x); v[j].y = __bfloat162float(h0.y);
        v[j].z = __bfloat162float(h1.x); v[j].w = __bfloat162float(h1.y);
        s += (v[j].x + v[j].y) + (v[j].z + v[j].w);
    }
    #pragma unroll
    for (int o = 16; o; o >>= 1) s += __shfl_xor_sync(~0u, s, o);
    float mu = s * (1.f / 384.f), q = 0.f;
    #pragma unroll
    for (int j = 0; j < 3; j++) {
        v[j].x -= mu; v[j].y -= mu; v[j].z -= mu; v[j].w -= mu;
        q += v[j].x * v[j].x + v[j].y * v[j].y + v[j].z * v[j].z + v[j].w * v[j].w;
    }
    #pragma unroll
    for (int o = 16; o; o >>= 1) q += __shfl_xor_sync(~0u, q, o);
    float rs = rsqrtf(q * (1.f / 384.f) + 1e-6f);
    #pragma unroll
    for (int j = 0; j < 3; j++) {
        int c = lane * 4 + j * 128;
        float4 wv = *(const float4*)(w + c);
        float4 bv = *(const float4*)(b + c);
        __nv_bfloat162 p0 = __floats2bfloat162_rn((v[j].x * rs * wv.x + bv.x) * scale,
                                                  (v[j].y * rs * wv.y + bv.y) * scale);
        __nv_bfloat162 p1 = __floats2bfloat162_rn((v[j].z * rs * wv.z + bv.z) * scale,
                                                  (v[j].w * rs * wv.w + bv.w) * scale);
        *(uint2*)(y + c) = make_uint2(*(uint32_t*)&p0, *(uint32_t*)&p1);
    }
}

// ---------------- mma.sync bf16 GEMM, 3-stage cp.async, single-sync loop ----------------
// C[m,n] = sum_k A[m,k]*B[n,k], A/B bf16 K-major. BM=BN=128, BK=32, 256 thr.
#define BM 128
#define BN 128
#define SROWB 80
#define STGB ((BM + BN) * SROWB)   // 20480 bytes per stage
#define NSTAGE 3
#define SMEMB (NSTAGE * STGB)      // 61440

#define EPI_QB    0   // +bias -> bf16
#define EPI_KV    1   // cols<384: +bias -> bf16 k ; cols>=384: +bias -> bf16 vt transposed
#define EPI_EXP   2   // exp(acc), mask cols>=curM -> bf16 (unnormalized softmax)
#define EPI_AVB   3   // acc / rowsum(probs) -> bf16   (rowsum from A tiles)
#define EPI_GELU  4   // +bias, gelu -> bf16
#define EPI_RES   5   // (acc+bias)*ls + C -> fp32

template<int EPI>
__global__ void __launch_bounds__(256, 2)
mma_gemm(const __nv_bfloat16* __restrict__ A, const __nv_bfloat16* __restrict__ B,
         const float* __restrict__ bias, const float* __restrict__ ls,
         void* __restrict__ Cv, void* __restrict__ Cv2,
         int M, int K, int lda, int ldb, int ldc, int curM,
         long strA, long strB, long strC, long strC2)
{
    extern __shared__ __align__(16) char smem_[];
    __shared__ float rinv[BM];          // per-row 1/sum for EPI_AVB
    A += (long)blockIdx.z * strA;
    B += (long)blockIdx.z * strB;
    int m0 = blockIdx.y * BM, n0 = blockIdx.x * BN;
    int t = threadIdx.x;
    int warp = t >> 5, lane = t & 31;
    int wm = warp & 1, wn = warp >> 1;

    float acc[4][4][4];
    #pragma unroll
    for (int i = 0; i < 4; i++)
        #pragma unroll
        for (int j = 0; j < 4; j++)
            #pragma unroll
            for (int q = 0; q < 4; q++) acc[i][j][q] = 0.f;

    uint32_t sb = (uint32_t)__cvta_generic_to_shared(smem_);
    int sRow = t >> 2, sCol = (t & 3) * 16;
    auto stage = [&](int kt) {
        uint32_t tA = sb + (uint32_t)((kt % NSTAGE) * STGB);
        uint32_t tB = tA + BM * SROWB;
        int k0 = kt * 32;
        #pragma unroll
        for (int i2 = 0; i2 < 2; i2++) {
            int row = sRow + i2 * 64;
            int gm = m0 + row; gm = gm < M ? gm : M - 1;
            cpa16(tA + (uint32_t)(row * SROWB + sCol), A + (long)gm * lda + k0 + sCol / 2);
        }
        #pragma unroll
        for (int i2 = 0; i2 < 2; i2++) {
            int row = sRow + i2 * 64;
            cpa16(tB + (uint32_t)(row * SROWB + sCol), B + (long)(n0 + row) * ldb + k0 + sCol / 2);
        }
        cpa_commit();
    };

    const int T = K >> 5;
    stage(0); stage(1);

    uint32_t aOff = (uint32_t)((wm * 64 + (lane & 15)) * SROWB + (lane >> 4) * 16);
    uint32_t bOff = (uint32_t)(BM * SROWB + (wn * 32 + (lane & 7)) * SROWB + ((lane >> 3) & 1) * 16);

    float psum = 0.f;   // EPI_AVB: per-thread partial prob-row sum (half row t>>1)

    for (int i = 0; i < T; i++) {
        asm volatile("cp.async.wait_group 1;" ::: "memory");
        __syncthreads();    // single barrier: orders compute(i-1) before stage(i+2)
        if (EPI == EPI_AVB) {
            const __nv_bfloat16* arow = (const __nv_bfloat16*)
                (smem_ + (size_t)(i % NSTAGE) * STGB + (t >> 1) * SROWB + (t & 1) * 32);
            #pragma unroll
            for (int z = 0; z < 4; z++) {
                uint2 u = *(const uint2*)(arow + z * 4);
                __nv_bfloat162 a0 = *(__nv_bfloat162*)&u.x;
                __nv_bfloat162 a1 = *(__nv_bfloat162*)&u.y;
                psum += (__bfloat162float(a0.x) + __bfloat162float(a0.y))
                      + (__bfloat162float(a1.x) + __bfloat162float(a1.y));
            }
        }
        if (i + 2 < T) stage(i + 2);
        else cpa_commit();
        uint32_t tbase = sb + (uint32_t)((i % NSTAGE) * STGB);
        #pragma unroll
        for (int kk = 0; kk < 2; kk++) {
            uint32_t af[4][4], bf_[4][2];
            #pragma unroll
            for (int mt = 0; mt < 4; mt++)
                ldm4(af[mt], tbase + aOff + (uint32_t)(mt * 16 * SROWB + kk * 32));
            #pragma unroll
            for (int nt = 0; nt < 4; nt++)
                ldm2(bf_[nt], tbase + bOff + (uint32_t)(nt * 8 * SROWB + kk * 32));
            #pragma unroll
            for (int mt = 0; mt < 4; mt++)
                #pragma unroll
                for (int nt = 0; nt < 4; nt++)
                    mma16816(acc[mt][nt], af[mt], bf_[nt]);
        }
    }
    __syncthreads();

    if (EPI == EPI_AVB) {
        psum += __shfl_xor_sync(~0u, psum, 1);   // combine the two half-rows
        if ((t & 1) == 0) rinv[t >> 1] = 1.f / psum;
        __syncthreads();
    }

    // ---- epilogue ----
    int g = lane >> 2, tg = lane & 3;
    #pragma unroll
    for (int mt = 0; mt < 4; mt++) {
        #pragma unroll
        for (int nt = 0; nt < 4; nt++) {
            int gm = m0 + wm * 64 + mt * 16 + g;
            int gn = n0 + wn * 32 + nt * 8 + tg * 2;
            float* cc = acc[mt][nt];
            float b0 = 0.f, b1 = 0.f, l0 = 0.f, l1 = 0.f;
            if (EPI == EPI_QB || EPI == EPI_KV || EPI == EPI_GELU || EPI == EPI_RES) {
                float2 bv = *(const float2*)&bias[gn]; b0 = bv.x; b1 = bv.y;
            }
            if (EPI == EPI_RES) { float2 lv = *(const float2*)&ls[gn]; l0 = lv.x; l1 = lv.y; }
            #pragma unroll
            for (int h = 0; h < 2; h++) {
                int gmh = gm + h * 8;
                if (gmh >= M) continue;
                float v0 = cc[h * 2 + 0], v1 = cc[h * 2 + 1];
                if (EPI == EPI_QB) {
                    __nv_bfloat16* C = (__nv_bfloat16*)Cv + (long)blockIdx.z * strC;
                    __nv_bfloat162 p = __floats2bfloat162_rn(v0 + b0, v1 + b1);
                    *(uint32_t*)&C[(long)gmh * ldc + gn] = *(uint32_t*)&p;
                } else if (EPI == EPI_KV) {
                    if (gn < DD) {
                        __nv_bfloat16* C = (__nv_bfloat16*)Cv + (long)blockIdx.z * strC;
                        __nv_bfloat162 p = __floats2bfloat162_rn(v0 + b0, v1 + b1);
                        *(uint32_t*)&C[(long)gmh * ldc + gn] = *(uint32_t*)&p;
                    } else {
                        __nv_bfloat16* C2 = (__nv_bfloat16*)Cv2 + (long)blockIdx.z * strC2;
                        int vn = gn - DD;
                        C2[(long)vn * KPAD + gmh]       = __float2bfloat16(v0 + b0);
                        C2[(long)(vn + 1) * KPAD + gmh] = __float2bfloat16(v1 + b1);
                    }
                } else if (EPI == EPI_EXP) {
                    __nv_bfloat16* C = (__nv_bfloat16*)Cv + (long)blockIdx.z * strC;
                    float e0 = (gn < curM)     ? __expf(v0) : 0.f;
                    float e1 = (gn + 1 < curM) ? __expf(v1) : 0.f;
                    __nv_bfloat162 p = __floats2bfloat162_rn(e0, e1);
                    *(uint32_t*)&C[(long)gmh * ldc + gn] = *(uint32_t*)&p;
                } else if (EPI == EPI_AVB) {
                    __nv_bfloat16* C = (__nv_bfloat16*)Cv + (long)blockIdx.z * strC;
                    float inv = rinv[gmh - m0];
                    __nv_bfloat162 p = __floats2bfloat162_rn(v0 * inv, v1 * inv);
                    *(uint32_t*)&C[(long)gmh * ldc + gn] = *(uint32_t*)&p;
                } else if (EPI == EPI_RES) {
                    float* C = (float*)Cv + (long)blockIdx.z * strC;
                    long ci = (long)gmh * ldc + gn;
                    float2 old = *(float2*)&C[ci];
                    *(float2*)&C[ci] = make_float2((v0 + b0) * l0 + old.x,
                                                   (v1 + b1) * l1 + old.y);
                } else {   // EPI_GELU
                    __nv_bfloat16* C = (__nv_bfloat16*)Cv + (long)blockIdx.z * strC;
                    v0 += b0; v1 += b1;
                    v0 = 0.5f * v0 * (1.f + erff(v0 * 0.70710678118654752f));
                    v1 = 0.5f * v1 * (1.f + erff(v1 * 0.70710678118654752f));
                    __nv_bfloat162 p = __floats2bfloat162_rn(v0, v1);
                    *(uint32_t*)&C[(long)gmh * ldc + gn] = *(uint32_t*)&p;
                }
            }
        }
    }
}

// ---------------- host ----------------
extern "C" void kernel_launch(void* const* d_in, const int* in_sizes, int n_in,
                              void* d_out, int out_size)
{
    const float* x_in = (const float*)d_in[0];
    const float* n1w = (const float*)d_in[1];  const float* n1b = (const float*)d_in[2];
    const float* qkvw = (const float*)d_in[3]; const float* qkvb = (const float*)d_in[4];
    const float* qnw = (const float*)d_in[5];  const float* qnb = (const float*)d_in[6];
    const float* knw = (const float*)d_in[7];  const float* knb = (const float*)d_in[8];
    const float* anw = (const float*)d_in[9];  const float* anb = (const float*)d_in[10];
    const float* projw = (const float*)d_in[11]; const float* projb = (const float*)d_in[12];
    const float* ls1 = (const float*)d_in[13];
    const float* n2w = (const float*)d_in[14]; const float* n2b = (const float*)d_in[15];
    const float* fc1w = (const float*)d_in[16]; const float* fc1b = (const float*)d_in[17];
    const float* fc2w = (const float*)d_in[18]; const float* fc2b = (const float*)d_in[19];
    const float* ls2 = (const float*)d_in[20];

    float *gx;
    __nv_bfloat16 *bxn, *bq, *bqr, *bk, *bkr, *bmem, *bvt, *battn, *bavr, *btmp, *bh;
    __nv_bfloat16 *wq, *wp, *w1, *w2;
    cudaGetSymbolAddress((void**)&gx, g_x);
    cudaGetSymbolAddress((void**)&bxn, b_xn);   cudaGetSymbolAddress((void**)&bq, b_q);
    cudaGetSymbolAddress((void**)&bqr, b_qraw); cudaGetSymbolAddress((void**)&bk, b_k);
    cudaGetSymbolAddress((void**)&bkr, b_kraw); cudaGetSymbolAddress((void**)&bmem, b_mem);
    cudaGetSymbolAddress((void**)&bvt, b_vt);   cudaGetSymbolAddress((void**)&battn, b_attn);
    cudaGetSymbolAddress((void**)&bavr, b_avraw);cudaGetSymbolAddress((void**)&btmp, b_tmp);
    cudaGetSymbolAddress((void**)&bh, b_h);
    cudaGetSymbolAddress((void**)&wq, w_qkv);   cudaGetSymbolAddress((void**)&wp, w_proj);
    cudaGetSymbolAddress((void**)&w1, w_fc1);   cudaGetSymbolAddress((void**)&w2, w_fc2);

    cudaFuncSetAttribute(mma_gemm<EPI_QB>,   cudaFuncAttributeMaxDynamicSharedMemorySize, SMEMB);
    cudaFuncSetAttribute(mma_gemm<EPI_KV>,   cudaFuncAttributeMaxDynamicSharedMemorySize, SMEMB);
    cudaFuncSetAttribute(mma_gemm<EPI_EXP>,  cudaFuncAttributeMaxDynamicSharedMemorySize, SMEMB);
    cudaFuncSetAttribute(mma_gemm<EPI_AVB>,  cudaFuncAttributeMaxDynamicSharedMemorySize, SMEMB);
    cudaFuncSetAttribute(mma_gemm<EPI_GELU>, cudaFuncAttributeMaxDynamicSharedMemorySize, SMEMB);
    cudaFuncSetAttribute(mma_gemm<EPI_RES>,  cudaFuncAttributeMaxDynamicSharedMemorySize, SMEMB);

    int n;
    n = LL * 3 * DD * DD; f2bf<<<(n / 4 + 255) / 256, 256>>>(qkvw, wq, n);
    n = LL * DD * DD;     f2bf<<<(n / 4 + 255) / 256, 256>>>(projw, wp, n);
    n = LL * HH * DD;     f2bf<<<(n / 4 + 255) / 256, 256>>>(fc1w, w1, n);
    n = LL * DD * HH;     f2bf<<<(n / 4 + 255) / 256, 256>>>(fc2w, w2, n);

    const float scale = 1.0f / sqrtf((float)DD);
    const long xS = (long)NPTS * DD, mS = (long)KPAD * DD;
    const long vtS = (long)DD * KPAD, aS = (long)NPTS * KPAD;
    const int Mflat = BB * NPTS;                 // 18464
    const int KAV = 608;                          // covers curM<=581, mult of 32
    const dim3 gFlatD(3, 145, 1), gFlatH(12, 145, 1);

    for (int r = 0; r < 4; r++) {
        int curM = NPTS + r;
        build_x_mem<<<dim3(NPTS, BB), DD>>>(x_in, gx, bmem, r);
        for (int l = 0; l < LL; l++) {
            const __nv_bfloat16* Wq = wq + (long)l * 3 * DD * DD;
            const __nv_bfloat16* Wkv = Wq + (long)DD * DD;      // rows D..3D contiguous
            const float* bqp = qkvb + (long)l * 3 * DD;
            const float* bkvp = bqp + DD;                       // k bias then v bias

            // xn = LN(x, norm1) -> bf16
            ln_f32<<<(Mflat + 7) / 8, 256>>>(gx, n1w + l * DD, n1b + l * DD, bxn,
                Mflat, 0, 0, 1.f);
            // q = xn @ Wq^T + bq -> bf16 ; q-LN (scale folded) -> bf16
            mma_gemm<EPI_QB><<<gFlatD, 256, SMEMB>>>(bxn, Wq, bqp, nullptr, bqr, nullptr,
                Mflat, DD, DD, DD, DD, 0, 0, 0, 0, 0);
            ln_b16<<<(Mflat + 7) / 8, 256>>>(bqr, qnw + l * DD, qnb + l * DD, bq,
                Mflat, 0, 0, scale);
            // fused K+V: [k | v] = mem @ [Wk;Wv]^T + [bk;bv]
            dim3 gKV(6, 5, BB);
            mma_gemm<EPI_KV><<<gKV, 256, SMEMB>>>(bmem, Wkv, bkvp, nullptr, bkr, bvt,
                curM, DD, DD, DD, DD, 0, mS, 0, mS, vtS);
            ln_b16<<<dim3((curM + 7) / 8, 1, BB), 256>>>(bkr, knw + l * DD, knb + l * DD, bk,
                curM, mS, mS, 1.f);
            // probs = exp(q_scaled @ k^T), masked cols>=curM -> bf16 (unnormalized)
            dim3 gLog(5, 5, BB);
            mma_gemm<EPI_EXP><<<gLog, 256, SMEMB>>>(bq, bk, nullptr, nullptr, battn, nullptr,
                NPTS, DD, DD, DD, KPAD, curM, xS, mS, aS, 0);
            // prod = (probs @ vT^T) / rowsum(probs) -> bf16
            dim3 gProd(3, 5, BB);
            mma_gemm<EPI_AVB><<<gProd, 256, SMEMB>>>(battn, bvt, nullptr, nullptr, bavr, nullptr,
                NPTS, KAV, KPAD, KPAD, DD, 0, aS, vtS, xS, 0);
            // an-LN -> bf16
            ln_b16<<<dim3((NPTS + 7) / 8, 1, BB), 256>>>(bavr, anw + l * DD, anb + l * DD, btmp,
                NPTS, xS, xS, 1.f);
            // x += (prodn @ proj^T + pb) * ls1
            mma_gemm<EPI_RES><<<gFlatD, 256, SMEMB>>>(btmp, wp + (long)l * DD * DD,
                projb + l * DD, ls1 + l * DD, gx, nullptr,
                Mflat, DD, DD, DD, DD, 0, 0, 0, 0, 0);
            // norm2 -> bf16
            ln_f32<<<(Mflat + 7) / 8, 256>>>(gx, n2w + l * DD, n2b + l * DD, bxn,
                Mflat, 0, 0, 1.f);
            // h = gelu(xn @ fc1^T + b1) -> bf16
            mma_gemm<EPI_GELU><<<gFlatH, 256, SMEMB>>>(bxn, w1 + (long)l * HH * DD,
                fc1b + (long)l * HH, nullptr, bh, nullptr,
                Mflat, DD, DD, DD, HH, 0, 0, 0, 0, 0);
            // x += (h @ fc2^T + b2) * ls2
            mma_gemm<EPI_RES><<<gFlatD, 256, SMEMB>>>(bh, w2 + (long)l * DD * HH,
                fc2b + l * DD, ls2 + l * DD, gx, nullptr,
                Mflat, HH, HH, HH, DD, 0, 0, 0, 0, 0);
        }
    }
    cudaMemcpyAsync(d_out, gx, (size_t)BB * NPTS * DD * sizeof(float),
                    cudaMemcpyDeviceToDevice);
}

// round 16
// speedup vs baseline: 1.2022x; 1.0316x over previous
#include <cuda_runtime.h>
#include <cuda_bf16.h>
#include <math.h>
#include <stdint.h>

#define BB   32
#define NPTS 577
#define DD   384
#define HH   1536
#define LL   12
#define KPAD 640

// ---------------- scratch (device globals; no allocs) ----------------
__device__ __align__(256) float g_x  [BB * NPTS * DD];
__device__ __align__(256) __nv_bfloat16 b_xn  [BB * NPTS * DD];
__device__ __align__(256) __nv_bfloat16 b_q   [BB * NPTS * DD];
__device__ __align__(256) __nv_bfloat16 b_qraw[BB * NPTS * DD];
__device__ __align__(256) __nv_bfloat16 b_k   [BB * KPAD * DD];
__device__ __align__(256) __nv_bfloat16 b_kraw[BB * KPAD * DD];
__device__ __align__(256) __nv_bfloat16 b_mem [BB * KPAD * DD];
__device__ __align__(256) __nv_bfloat16 b_vt  [BB * DD * KPAD];
__device__ __align__(256) __nv_bfloat16 b_attn[BB * NPTS * KPAD];
__device__ __align__(256) __nv_bfloat16 b_avraw[BB * NPTS * DD];
__device__ __align__(256) __nv_bfloat16 b_tmp [BB * NPTS * DD];
__device__ __align__(256) __nv_bfloat16 b_h   [BB * NPTS * HH];
__device__ __align__(256) __nv_bfloat16 w_qkv [LL * 3 * DD * DD];
__device__ __align__(256) __nv_bfloat16 w_proj[LL * DD * DD];
__device__ __align__(256) __nv_bfloat16 w_fc1 [LL * HH * DD];
__device__ __align__(256) __nv_bfloat16 w_fc2 [LL * DD * HH];

// ---------------- PTX helpers (base ISA only) ----------------
__device__ __forceinline__ void cpa16(uint32_t s, const void* g) {
    asm volatile("cp.async.cg.shared.global [%0], [%1], 16;" :: "r"(s), "l"(g));
}
__device__ __forceinline__ void cpa_commit() {
    asm volatile("cp.async.commit_group;" ::: "memory");
}
__device__ __forceinline__ void ldm4(uint32_t* r, uint32_t addr) {
    asm volatile("ldmatrix.sync.aligned.m8n8.x4.shared.b16 {%0,%1,%2,%3}, [%4];"
        : "=r"(r[0]), "=r"(r[1]), "=r"(r[2]), "=r"(r[3]) : "r"(addr));
}
__device__ __forceinline__ void ldm2(uint32_t* r, uint32_t addr) {
    asm volatile("ldmatrix.sync.aligned.m8n8.x2.shared.b16 {%0,%1}, [%2];"
        : "=r"(r[0]), "=r"(r[1]) : "r"(addr));
}
__device__ __forceinline__ void mma16816(float* c, const uint32_t* a, const uint32_t* b) {
    asm volatile("mma.sync.aligned.m16n8k16.row.col.f32.bf16.bf16.f32 "
        "{%0,%1,%2,%3}, {%4,%5,%6,%7}, {%8,%9}, {%0,%1,%2,%3};"
        : "+f"(c[0]), "+f"(c[1]), "+f"(c[2]), "+f"(c[3])
        : "r"(a[0]), "r"(a[1]), "r"(a[2]), "r"(a[3]), "r"(b[0]), "r"(b[1]));
}

// ---------------- elementwise kernels ----------------
__global__ void f2bf(const float* __restrict__ in, __nv_bfloat16* __restrict__ out, int n) {
    int i = (blockIdx.x * 256 + threadIdx.x) * 4;
    if (i >= n) return;
    float4 v = *(const float4*)(in + i);
    __nv_bfloat162 p0 = __floats2bfloat162_rn(v.x, v.y);
    __nv_bfloat162 p1 = __floats2bfloat162_rn(v.z, v.w);
    *(uint2*)(out + i) = make_uint2(*(uint32_t*)&p0, *(uint32_t*)&p1);
}

__global__ void build_x_mem(const float* __restrict__ inp, float* __restrict__ x,
                            __nv_bfloat16* __restrict__ mem, int r) {
    int d = threadIdx.x, n = blockIdx.x, b = blockIdx.y;
    long xi = ((long)b * NPTS + n) * DD + d;
    long mi = ((long)b * KPAD + n) * DD + d;
    if (n == 0) {
        float val = (r == 0) ? inp[xi] : x[xi];
        x[xi] = val;
        __nv_bfloat16 bv = __float2bfloat16(val);
        mem[mi] = bv;
        mem[((long)b * KPAD + NPTS + r) * DD + d] = bv;
    } else {
        float val = inp[xi];
        x[xi] = val;
        mem[mi] = __float2bfloat16(val);
    }
}

// warp-per-row LN, fp32 in -> bf16 out
__global__ void ln_f32(const float* __restrict__ in, const float* __restrict__ w,
                       const float* __restrict__ b, __nv_bfloat16* __restrict__ out,
                       int rows, long strIn, long strOut, float scale) {
    int warp = threadIdx.x >> 5, lane = threadIdx.x & 31;
    int row = blockIdx.x * 8 + warp;
    if (row >= rows) return;
    const float* x = in + (long)blockIdx.y * strIn + (long)row * DD;
    __nv_bfloat16* y = out + (long)blockIdx.y * strOut + (long)row * DD;
    float4 v[3]; float s = 0.f;
    #pragma unroll
    for (int j = 0; j < 3; j++) {
        v[j] = *(const float4*)(x + lane * 4 + j * 128);
        s += (v[j].x + v[j].y) + (v[j].z + v[j].w);
    }
    #pragma unroll
    for (int o = 16; o; o >>= 1) s += __shfl_xor_sync(~0u, s, o);
    float mu = s * (1.f / 384.f), q = 0.f;
    #pragma unroll
    for (int j = 0; j < 3; j++) {
        v[j].x -= mu; v[j].y -= mu; v[j].z -= mu; v[j].w -= mu;
        q += v[j].x * v[j].x + v[j].y * v[j].y + v[j].z * v[j].z + v[j].w * v[j].w;
    }
    #pragma unroll
    for (int o = 16; o; o >>= 1) q += __shfl_xor_sync(~0u, q, o);
    float rs = rsqrtf(q * (1.f / 384.f) + 1e-6f);
    #pragma unroll
    for (int j = 0; j < 3; j++) {
        int c = lane * 4 + j * 128;
        float4 wv = *(const float4*)(w + c);
        float4 bv = *(const float4*)(b + c);
        __nv_bfloat162 p0 = __floats2bfloat162_rn((v[j].x * rs * wv.x + bv.x) * scale,
                                                  (v[j].y * rs * wv.y + bv.y) * scale);
        __nv_bfloat162 p1 = __floats2bfloat162_rn((v[j].z * rs * wv.z + bv.z) * scale,
                                                  (v[j].w * rs * wv.w + bv.w) * scale);
        *(uint2*)(y + c) = make_uint2(*(uint32_t*)&p0, *(uint32_t*)&p1);
    }
}

// LN body on bf16 row (device inline)
__device__ __forceinline__ void ln_row_b16(const __nv_bfloat16* __restrict__ x,
                                           const float* __restrict__ w,
                                           const float* __restrict__ b,
                                           __nv_bfloat16* __restrict__ y,
                                           int lane, float scale) {
    float4 v[3]; float s = 0.f;
    #pragma unroll
    for (int j = 0; j < 3; j++) {
        uint2 u = *(const uint2*)(x + lane * 4 + j * 128);
        __nv_bfloat162 h0 = *(__nv_bfloat162*)&u.x;
        __nv_bfloat162 h1 = *(__nv_bfloat162*)&u.y;
        v[j].x = __bfloat162float(h0.x); v[j].y = __bfloat162float(h0.y);
        v[j].z = __bfloat162float(h1.x); v[j].w = __bfloat162float(h1.y);
        s += (v[j].x + v[j].y) + (v[j].z + v[j].w);
    }
    #pragma unroll
    for (int o = 16; o; o >>= 1) s += __shfl_xor_sync(~0u, s, o);
    float mu = s * (1.f / 384.f), q = 0.f;
    #pragma unroll
    for (int j = 0; j < 3; j++) {
        v[j].x -= mu; v[j].y -= mu; v[j].z -= mu; v[j].w -= mu;
        q += v[j].x * v[j].x + v[j].y * v[j].y + v[j].z * v[j].z + v[j].w * v[j].w;
    }
    #pragma unroll
    for (int o = 16; o; o >>= 1) q += __shfl_xor_sync(~0u, q, o);
    float rs = rsqrtf(q * (1.f / 384.f) + 1e-6f);
    #pragma unroll
    for (int j = 0; j < 3; j++) {
        int c = lane * 4 + j * 128;
        float4 wv = *(const float4*)(w + c);
        float4 bv = *(const float4*)(b + c);
        __nv_bfloat162 p0 = __floats2bfloat162_rn((v[j].x * rs * wv.x + bv.x) * scale,
                                                  (v[j].y * rs * wv.y + bv.y) * scale);
        __nv_bfloat162 p1 = __floats2bfloat162_rn((v[j].z * rs * wv.z + bv.z) * scale,
                                                  (v[j].w * rs * wv.w + bv.w) * scale);
        *(uint2*)(y + c) = make_uint2(*(uint32_t*)&p0, *(uint32_t*)&p1);
    }
}

// warp-per-row LN, bf16 in -> bf16 out (an-LN standalone)
__global__ void ln_b16(const __nv_bfloat16* __restrict__ in, const float* __restrict__ w,
                       const float* __restrict__ b, __nv_bfloat16* __restrict__ out,
                       int rows, long strIn, long strOut, float scale) {
    int warp = threadIdx.x >> 5, lane = threadIdx.x & 31;
    int row = blockIdx.x * 8 + warp;
    if (row >= rows) return;
    ln_row_b16(in + (long)blockIdx.y * strIn + (long)row * DD, w, b,
               out + (long)blockIdx.y * strOut + (long)row * DD, lane, scale);
}

// fused q-LN + k-LN in one launch (dispatcher)
__global__ void ln_qk(const __nv_bfloat16* __restrict__ bqr, const float* __restrict__ qw,
                      const float* __restrict__ qb, __nv_bfloat16* __restrict__ bq,
                      int Mq, float scale,
                      const __nv_bfloat16* __restrict__ bkr, const float* __restrict__ kw,
                      const float* __restrict__ kb, __nv_bfloat16* __restrict__ bk,
                      int curM, long mS, int nQ, int nKB) {
    int warp = threadIdx.x >> 5, lane = threadIdx.x & 31;
    int bid = blockIdx.x;
    if (bid < nQ) {
        int row = bid * 8 + warp;
        if (row >= Mq) return;
        ln_row_b16(bqr + (long)row * DD, qw, qb, bq + (long)row * DD, lane, scale);
    } else {
        int idx = bid - nQ;
        int bz = idx / nKB, blk = idx % nKB;
        int row = blk * 8 + warp;
        if (row >= curM) return;
        long off = (long)bz * mS + (long)row * DD;
        ln_row_b16(bkr + off, kw, kb, bk + off, lane, 1.f);
    }
}

// ---------------- mma.sync bf16 GEMM, 3-stage cp.async, single-sync loop ----------------
#define BM 128
#define BN 128
#define SROWB 80
#define STGB ((BM + BN) * SROWB)   // 20480 bytes per stage
#define NSTAGE 3
#define SMEMB (NSTAGE * STGB)      // 61440

#define EPI_EXP   2   // exp(acc), mask cols>=curM -> bf16
#define EPI_AVB   3   // acc / rowsum(probs) -> bf16
#define EPI_GELU  4   // +bias, gelu -> bf16
#define EPI_RES   5   // (acc+bias)*ls + C -> fp32

template<int EPI>
__global__ void __launch_bounds__(256, 2)
mma_gemm(const __nv_bfloat16* __restrict__ A, const __nv_bfloat16* __restrict__ B,
         const float* __restrict__ bias, const float* __restrict__ ls,
         void* __restrict__ Cv, void* __restrict__ Cv2,
         int M, int K, int lda, int ldb, int ldc, int curM,
         long strA, long strB, long strC, long strC2)
{
    extern __shared__ __align__(16) char smem_[];
    __shared__ float rinv[BM];
    A += (long)blockIdx.z * strA;
    B += (long)blockIdx.z * strB;
    int m0 = blockIdx.y * BM, n0 = blockIdx.x * BN;
    int t = threadIdx.x;
    int warp = t >> 5, lane = t & 31;
    int wm = warp & 1, wn = warp >> 1;

    float acc[4][4][4];
    #pragma unroll
    for (int i = 0; i < 4; i++)
        #pragma unroll
        for (int j = 0; j < 4; j++)
            #pragma unroll
            for (int q = 0; q < 4; q++) acc[i][j][q] = 0.f;

    uint32_t sb = (uint32_t)__cvta_generic_to_shared(smem_);
    int sRow = t >> 2, sCol = (t & 3) * 16;
    auto stage = [&](int kt) {
        uint32_t tA = sb + (uint32_t)((kt % NSTAGE) * STGB);
        uint32_t tB = tA + BM * SROWB;
        int k0 = kt * 32;
        #pragma unroll
        for (int i2 = 0; i2 < 2; i2++) {
            int row = sRow + i2 * 64;
            int gm = m0 + row; gm = gm < M ? gm : M - 1;
            cpa16(tA + (uint32_t)(row * SROWB + sCol), A + (long)gm * lda + k0 + sCol / 2);
        }
        #pragma unroll
        for (int i2 = 0; i2 < 2; i2++) {
            int row = sRow + i2 * 64;
            cpa16(tB + (uint32_t)(row * SROWB + sCol), B + (long)(n0 + row) * ldb + k0 + sCol / 2);
        }
        cpa_commit();
    };

    const int T = K >> 5;
    stage(0); stage(1);

    uint32_t aOff = (uint32_t)((wm * 64 + (lane & 15)) * SROWB + (lane >> 4) * 16);
    uint32_t bOff = (uint32_t)(BM * SROWB + (wn * 32 + (lane & 7)) * SROWB + ((lane >> 3) & 1) * 16);

    float psum = 0.f;

    for (int i = 0; i < T; i++) {
        asm volatile("cp.async.wait_group 1;" ::: "memory");
        __syncthreads();
        if (EPI == EPI_AVB) {
            const __nv_bfloat16* arow = (const __nv_bfloat16*)
                (smem_ + (size_t)(i % NSTAGE) * STGB + (t >> 1) * SROWB + (t & 1) * 32);
            #pragma unroll
            for (int z = 0; z < 4; z++) {
                uint2 u = *(const uint2*)(arow + z * 4);
                __nv_bfloat162 a0 = *(__nv_bfloat162*)&u.x;
                __nv_bfloat162 a1 = *(__nv_bfloat162*)&u.y;
                psum += (__bfloat162float(a0.x) + __bfloat162float(a0.y))
                      + (__bfloat162float(a1.x) + __bfloat162float(a1.y));
            }
        }
        if (i + 2 < T) stage(i + 2);
        else cpa_commit();
        uint32_t tbase = sb + (uint32_t)((i % NSTAGE) * STGB);
        #pragma unroll
        for (int kk = 0; kk < 2; kk++) {
            uint32_t af[4][4], bf_[4][2];
            #pragma unroll
            for (int mt = 0; mt < 4; mt++)
                ldm4(af[mt], tbase + aOff + (uint32_t)(mt * 16 * SROWB + kk * 32));
            #pragma unroll
            for (int nt = 0; nt < 4; nt++)
                ldm2(bf_[nt], tbase + bOff + (uint32_t)(nt * 8 * SROWB + kk * 32));
            #pragma unroll
            for (int mt = 0; mt < 4; mt++)
                #pragma unroll
                for (int nt = 0; nt < 4; nt++)
                    mma16816(acc[mt][nt], af[mt], bf_[nt]);
        }
    }
    __syncthreads();

    if (EPI == EPI_AVB) {
        psum += __shfl_xor_sync(~0u, psum, 1);
        if ((t & 1) == 0) rinv[t >> 1] = 1.f / psum;
        __syncthreads();
    }

    int g = lane >> 2, tg = lane & 3;
    #pragma unroll
    for (int mt = 0; mt < 4; mt++) {
        #pragma unroll
        for (int nt = 0; nt < 4; nt++) {
            int gm = m0 + wm * 64 + mt * 16 + g;
            int gn = n0 + wn * 32 + nt * 8 + tg * 2;
            float* cc = acc[mt][nt];
            float b0 = 0.f, b1 = 0.f, l0 = 0.f, l1 = 0.f;
            if (EPI == EPI_GELU || EPI == EPI_RES) {
                float2 bv = *(const float2*)&bias[gn]; b0 = bv.x; b1 = bv.y;
            }
            if (EPI == EPI_RES) { float2 lv = *(const float2*)&ls[gn]; l0 = lv.x; l1 = lv.y; }
            #pragma unroll
            for (int h = 0; h < 2; h++) {
                int gmh = gm + h * 8;
                if (gmh >= M) continue;
                float v0 = cc[h * 2 + 0], v1 = cc[h * 2 + 1];
                if (EPI == EPI_EXP) {
                    __nv_bfloat16* C = (__nv_bfloat16*)Cv + (long)blockIdx.z * strC;
                    float e0 = (gn < curM)     ? __expf(v0) : 0.f;
                    float e1 = (gn + 1 < curM) ? __expf(v1) : 0.f;
                    __nv_bfloat162 p = __floats2bfloat162_rn(e0, e1);
                    *(uint32_t*)&C[(long)gmh * ldc + gn] = *(uint32_t*)&p;
                } else if (EPI == EPI_AVB) {
                    __nv_bfloat16* C = (__nv_bfloat16*)Cv + (long)blockIdx.z * strC;
                    float inv = rinv[gmh - m0];
                    __nv_bfloat162 p = __floats2bfloat162_rn(v0 * inv, v1 * inv);
                    *(uint32_t*)&C[(long)gmh * ldc + gn] = *(uint32_t*)&p;
                } else if (EPI == EPI_RES) {
                    float* C = (float*)Cv + (long)blockIdx.z * strC;
                    long ci = (long)gmh * ldc + gn;
                    float2 old = *(float2*)&C[ci];
                    *(float2*)&C[ci] = make_float2((v0 + b0) * l0 + old.x,
                                                   (v1 + b1) * l1 + old.y);
                } else {   // EPI_GELU
                    __nv_bfloat16* C = (__nv_bfloat16*)Cv + (long)blockIdx.z * strC;
                    v0 += b0; v1 += b1;
                    v0 = 0.5f * v0 * (1.f + erff(v0 * 0.70710678118654752f));
                    v1 = 0.5f * v1 * (1.f + erff(v1 * 0.70710678118654752f));
                    __nv_bfloat162 p = __floats2bfloat162_rn(v0, v1);
                    *(uint32_t*)&C[(long)gmh * ldc + gn] = *(uint32_t*)&p;
                }
            }
        }
    }
}

// ---------------- fused QB + KV GEMM (dispatcher; identical mainloop, K=384) ----------------
__global__ void __launch_bounds__(256, 2)
mma_qkv(const __nv_bfloat16* __restrict__ Axn, const __nv_bfloat16* __restrict__ Wq,
        const float* __restrict__ biasq,
        const __nv_bfloat16* __restrict__ Amem, const __nv_bfloat16* __restrict__ Wkv,
        const float* __restrict__ biaskv,
        __nv_bfloat16* __restrict__ Cq, __nv_bfloat16* __restrict__ Ck,
        __nv_bfloat16* __restrict__ Cvt,
        int Mq, int curM, int nQB, long mS, long vtS)
{
    extern __shared__ __align__(16) char smem_[];
    int bid = blockIdx.x;
    bool isQ = bid < nQB;
    const __nv_bfloat16 *A, *B;
    const float* bias;
    int M, m0, n0;
    long zC = 0;
    if (isQ) {
        int bx = bid % 3, by = bid / 3;
        A = Axn; B = Wq; bias = biasq; M = Mq;
        m0 = by * BM; n0 = bx * BN;
    } else {
        int idx = bid - nQB;
        int bx = idx % 6, by = (idx / 6) % 5;
        zC = idx / 30;
        A = Amem + zC * mS; B = Wkv; bias = biaskv; M = curM;
        m0 = by * BM; n0 = bx * BN;
    }
    int t = threadIdx.x;
    int warp = t >> 5, lane = t & 31;
    int wm = warp & 1, wn = warp >> 1;

    float acc[4][4][4];
    #pragma unroll
    for (int i = 0; i < 4; i++)
        #pragma unroll
        for (int j = 0; j < 4; j++)
            #pragma unroll
            for (int q = 0; q < 4; q++) acc[i][j][q] = 0.f;

    uint32_t sb = (uint32_t)__cvta_generic_to_shared(smem_);
    int sRow = t >> 2, sCol = (t & 3) * 16;
    auto stage = [&](int kt) {
        uint32_t tA = sb + (uint32_t)((kt % NSTAGE) * STGB);
        uint32_t tB = tA + BM * SROWB;
        int k0 = kt * 32;
        #pragma unroll
        for (int i2 = 0; i2 < 2; i2++) {
            int row = sRow + i2 * 64;
            int gm = m0 + row; gm = gm < M ? gm : M - 1;
            cpa16(tA + (uint32_t)(row * SROWB + sCol), A + (long)gm * DD + k0 + sCol / 2);
        }
        #pragma unroll
        for (int i2 = 0; i2 < 2; i2++) {
            int row = sRow + i2 * 64;
            cpa16(tB + (uint32_t)(row * SROWB + sCol), B + (long)(n0 + row) * DD + k0 + sCol / 2);
        }
        cpa_commit();
    };

    const int T = DD >> 5;    // 12
    stage(0); stage(1);

    uint32_t aOff = (uint32_t)((wm * 64 + (lane & 15)) * SROWB + (lane >> 4) * 16);
    uint32_t bOff = (uint32_t)(BM * SROWB + (wn * 32 + (lane & 7)) * SROWB + ((lane >> 3) & 1) * 16);

    for (int i = 0; i < T; i++) {
        asm volatile("cp.async.wait_group 1;" ::: "memory");
        __syncthreads();
        if (i + 2 < T) stage(i + 2);
        else cpa_commit();
        uint32_t tbase = sb + (uint32_t)((i % NSTAGE) * STGB);
        #pragma unroll
        for (int kk = 0; kk < 2; kk++) {
            uint32_t af[4][4], bf_[4][2];
            #pragma unroll
            for (int mt = 0; mt < 4; mt++)
                ldm4(af[mt], tbase + aOff + (uint32_t)(mt * 16 * SROWB + kk * 32));
            #pragma unroll
            for (int nt = 0; nt < 4; nt++)
                ldm2(bf_[nt], tbase + bOff + (uint32_t)(nt * 8 * SROWB + kk * 32));
            #pragma unroll
            for (int mt = 0; mt < 4; mt++)
                #pragma unroll
                for (int nt = 0; nt < 4; nt++)
                    mma16816(acc[mt][nt], af[mt], bf_[nt]);
        }
    }
    __syncthreads();

    int g = lane >> 2, tg = lane & 3;
    #pragma unroll
    for (int mt = 0; mt < 4; mt++) {
        #pragma unroll
        for (int nt = 0; nt < 4; nt++) {
            int gm = m0 + wm * 64 + mt * 16 + g;
            int gn = n0 + wn * 32 + nt * 8 + tg * 2;
            float* cc = acc[mt][nt];
            float2 bv = *(const float2*)&bias[gn];
            float b0 = bv.x, b1 = bv.y;
            #pragma unroll
            for (int h = 0; h < 2; h++) {
                int gmh = gm + h * 8;
                if (gmh >= M) continue;
                float v0 = cc[h * 2 + 0] + b0, v1 = cc[h * 2 + 1] + b1;
                if (isQ) {
                    __nv_bfloat162 p = __floats2bfloat162_rn(v0, v1);
                    *(uint32_t*)&Cq[(long)gmh * DD + gn] = *(uint32_t*)&p;
                } else if (gn < DD) {      // k path
                    __nv_bfloat16* C = Ck + zC * mS;
                    __nv_bfloat162 p = __floats2bfloat162_rn(v0, v1);
                    *(uint32_t*)&C[(long)gmh * DD + gn] = *(uint32_t*)&p;
                } else {                   // v path: transposed
                    __nv_bfloat16* C2 = Cvt + zC * vtS;
                    int vn = gn - DD;
                    C2[(long)vn * KPAD + gmh]       = __float2bfloat16(v0);
                    C2[(long)(vn + 1) * KPAD + gmh] = __float2bfloat16(v1);
                }
            }
        }
    }
}

// ---------------- host ----------------
extern "C" void kernel_launch(void* const* d_in, const int* in_sizes, int n_in,
                              void* d_out, int out_size)
{
    const float* x_in = (const float*)d_in[0];
    const float* n1w = (const float*)d_in[1];  const float* n1b = (const float*)d_in[2];
    const float* qkvw = (const float*)d_in[3]; const float* qkvb = (const float*)d_in[4];
    const float* qnw = (const float*)d_in[5];  const float* qnb = (const float*)d_in[6];
    const float* knw = (const float*)d_in[7];  const float* knb = (const float*)d_in[8];
    const float* anw = (const float*)d_in[9];  const float* anb = (const float*)d_in[10];
    const float* projw = (const float*)d_in[11]; const float* projb = (const float*)d_in[12];
    const float* ls1 = (const float*)d_in[13];
    const float* n2w = (const float*)d_in[14]; const float* n2b = (const float*)d_in[15];
    const float* fc1w = (const float*)d_in[16]; const float* fc1b = (const float*)d_in[17];
    const float* fc2w = (const float*)d_in[18]; const float* fc2b = (const float*)d_in[19];
    const float* ls2 = (const float*)d_in[20];

    float *gx;
    __nv_bfloat16 *bxn, *bq, *bqr, *bk, *bkr, *bmem, *bvt, *battn, *bavr, *btmp, *bh;
    __nv_bfloat16 *wq, *wp, *w1, *w2;
    cudaGetSymbolAddress((void**)&gx, g_x);
    cudaGetSymbolAddress((void**)&bxn, b_xn);   cudaGetSymbolAddress((void**)&bq, b_q);
    cudaGetSymbolAddress((void**)&bqr, b_qraw); cudaGetSymbolAddress((void**)&bk, b_k);
    cudaGetSymbolAddress((void**)&bkr, b_kraw); cudaGetSymbolAddress((void**)&bmem, b_mem);
    cudaGetSymbolAddress((void**)&bvt, b_vt);   cudaGetSymbolAddress((void**)&battn, b_attn);
    cudaGetSymbolAddress((void**)&bavr, b_avraw);cudaGetSymbolAddress((void**)&btmp, b_tmp);
    cudaGetSymbolAddress((void**)&bh, b_h);
    cudaGetSymbolAddress((void**)&wq, w_qkv);   cudaGetSymbolAddress((void**)&wp, w_proj);
    cudaGetSymbolAddress((void**)&w1, w_fc1);   cudaGetSymbolAddress((void**)&w2, w_fc2);

    cudaFuncSetAttribute(mma_qkv,            cudaFuncAttributeMaxDynamicSharedMemorySize, SMEMB);
    cudaFuncSetAttribute(mma_gemm<EPI_EXP>,  cudaFuncAttributeMaxDynamicSharedMemorySize, SMEMB);
    cudaFuncSetAttribute(mma_gemm<EPI_AVB>,  cudaFuncAttributeMaxDynamicSharedMemorySize, SMEMB);
    cudaFuncSetAttribute(mma_gemm<EPI_GELU>, cudaFuncAttributeMaxDynamicSharedMemorySize, SMEMB);
    cudaFuncSetAttribute(mma_gemm<EPI_RES>,  cudaFuncAttributeMaxDynamicSharedMemorySize, SMEMB);

    int n;
    n = LL * 3 * DD * DD; f2bf<<<(n / 4 + 255) / 256, 256>>>(qkvw, wq, n);
    n = LL * DD * DD;     f2bf<<<(n / 4 + 255) / 256, 256>>>(projw, wp, n);
    n = LL * HH * DD;     f2bf<<<(n / 4 + 255) / 256, 256>>>(fc1w, w1, n);
    n = LL * DD * HH;     f2bf<<<(n / 4 + 255) / 256, 256>>>(fc2w, w2, n);

    const float scale = 1.0f / sqrtf((float)DD);
    const long xS = (long)NPTS * DD, mS = (long)KPAD * DD;
    const long vtS = (long)DD * KPAD, aS = (long)NPTS * KPAD;
    const int Mflat = BB * NPTS;                 // 18464
    const int KAV = 608;
    const int nQB = 3 * 145;                      // 435 q-tiles
    const int nKV = 6 * 5 * BB;                   // 960 kv-tiles
    const dim3 gFlatD(3, 145, 1), gFlatH(12, 145, 1);

    for (int r = 0; r < 4; r++) {
        int curM = NPTS + r;
        int nKB = (curM + 7) / 8;                // 73
        build_x_mem<<<dim3(NPTS, BB), DD>>>(x_in, gx, bmem, r);
        for (int l = 0; l < LL; l++) {
            const __nv_bfloat16* Wq = wq + (long)l * 3 * DD * DD;
            const __nv_bfloat16* Wkv = Wq + (long)DD * DD;
            const float* bqp = qkvb + (long)l * 3 * DD;
            const float* bkvp = bqp + DD;

            // xn = LN(x, norm1) -> bf16
            ln_f32<<<(Mflat + 7) / 8, 256>>>(gx, n1w + l * DD, n1b + l * DD, bxn,
                Mflat, 0, 0, 1.f);
            // fused: q = xn@Wq^T+bq -> bqr  AND  [k|v] = mem@Wkv^T+bkv -> bkr / bvt
            mma_qkv<<<nQB + nKV, 256, SMEMB>>>(bxn, Wq, bqp, bmem, Wkv, bkvp,
                bqr, bkr, bvt, Mflat, curM, nQB, mS, vtS);
            // fused q-LN (scale folded) + k-LN
            ln_qk<<<2308 + nKB * BB, 256>>>(bqr, qnw + l * DD, qnb + l * DD, bq,
                Mflat, scale, bkr, knw + l * DD, knb + l * DD, bk, curM, mS, 2308, nKB);
            // probs = exp(q_scaled @ k^T), masked -> bf16 (unnormalized)
            dim3 gLog(5, 5, BB);
            mma_gemm<EPI_EXP><<<gLog, 256, SMEMB>>>(bq, bk, nullptr, nullptr, battn, nullptr,
                NPTS, DD, DD, DD, KPAD, curM, xS, mS, aS, 0);
            // prod = (probs @ vT^T) / rowsum(probs) -> bf16
            dim3 gProd(3, 5, BB);
            mma_gemm<EPI_AVB><<<gProd, 256, SMEMB>>>(battn, bvt, nullptr, nullptr, bavr, nullptr,
                NPTS, KAV, KPAD, KPAD, DD, 0, aS, vtS, xS, 0);
            // an-LN -> bf16
            ln_b16<<<dim3((NPTS + 7) / 8, 1, BB), 256>>>(bavr, anw + l * DD, anb + l * DD, btmp,
                NPTS, xS, xS, 1.f);
            // x += (prodn @ proj^T + pb) * ls1
            mma_gemm<EPI_RES><<<gFlatD, 256, SMEMB>>>(btmp, wp + (long)l * DD * DD,
                projb + l * DD, ls1 + l * DD, gx, nullptr,
                Mflat, DD, DD, DD, DD, 0, 0, 0, 0, 0);
            // norm2 -> bf16
            ln_f32<<<(Mflat + 7) / 8, 256>>>(gx, n2w + l * DD, n2b + l * DD, bxn,
                Mflat, 0, 0, 1.f);
            // h = gelu(xn @ fc1^T + b1) -> bf16
            mma_gemm<EPI_GELU><<<gFlatH, 256, SMEMB>>>(bxn, w1 + (long)l * HH * DD,
                fc1b + (long)l * HH, nullptr, bh, nullptr,
                Mflat, DD, DD, DD, HH, 0, 0, 0, 0, 0);
            // x += (h @ fc2^T + b2) * ls2
            mma_gemm<EPI_RES><<<gFlatD, 256, SMEMB>>>(bh, w2 + (long)l * DD * HH,
                fc2b + l * DD, ls2 + l * DD, gx, nullptr,
                Mflat, HH, HH, HH, DD, 0, 0, 0, 0, 0);
        }
    }
    cudaMemcpyAsync(d_out, gx, (size_t)BB * NPTS * DD * sizeof(float),
                    cudaMemcpyDeviceToDevice);
}

// round 17
// speedup vs baseline: 1.2537x; 1.0428x over previous
#include <cuda_runtime.h>
#include <cuda_bf16.h>
#include <cuda_fp8.h>
#include <math.h>
#include <stdint.h>

#define BB   32
#define NPTS 577
#define DD   384
#define HH   1536
#define LL   12
#define KPAD 640

// ---------------- scratch (device globals; no allocs) ----------------
__device__ __align__(256) float g_x  [BB * NPTS * DD];
__device__ __align__(256) __nv_bfloat16 b_xn  [BB * NPTS * DD];
__device__ __align__(256) __nv_bfloat16 b_q   [BB * NPTS * DD];
__device__ __align__(256) __nv_bfloat16 b_qraw[BB * NPTS * DD];
__device__ __align__(256) __nv_bfloat16 b_k   [BB * KPAD * DD];
__device__ __align__(256) __nv_bfloat16 b_kraw[BB * KPAD * DD];
__device__ __align__(256) __nv_bfloat16 b_mem [BB * KPAD * DD];
__device__ __align__(256) __nv_bfloat16 b_vt  [BB * DD * KPAD];
__device__ __align__(256) __nv_bfloat16 b_attn[BB * NPTS * KPAD];
__device__ __align__(256) __nv_bfloat16 b_avraw[BB * NPTS * DD];
__device__ __align__(256) __nv_bfloat16 w_qkv [LL * 3 * DD * DD];
// fp8 buffers (proj/fc1/fc2 path)
__device__ __align__(256) uint8_t f8_xn [BB * NPTS * DD];    // norm2 output
__device__ __align__(256) uint8_t f8_tmp[BB * NPTS * DD];    // an-LN output
__device__ __align__(256) uint8_t f8_h  [BB * NPTS * HH];    // gelu output
__device__ __align__(256) uint8_t w8_p  [LL * DD * DD];
__device__ __align__(256) uint8_t w8_1  [LL * HH * DD];
__device__ __align__(256) uint8_t w8_2  [LL * DD * HH];

// ---------------- PTX helpers (base ISA only) ----------------
__device__ __forceinline__ void cpa16(uint32_t s, const void* g) {
    asm volatile("cp.async.cg.shared.global [%0], [%1], 16;" :: "r"(s), "l"(g));
}
__device__ __forceinline__ void cpa_commit() {
    asm volatile("cp.async.commit_group;" ::: "memory");
}
__device__ __forceinline__ void ldm4(uint32_t* r, uint32_t addr) {
    asm volatile("ldmatrix.sync.aligned.m8n8.x4.shared.b16 {%0,%1,%2,%3}, [%4];"
        : "=r"(r[0]), "=r"(r[1]), "=r"(r[2]), "=r"(r[3]) : "r"(addr));
}
__device__ __forceinline__ void ldm2(uint32_t* r, uint32_t addr) {
    asm volatile("ldmatrix.sync.aligned.m8n8.x2.shared.b16 {%0,%1}, [%2];"
        : "=r"(r[0]), "=r"(r[1]) : "r"(addr));
}
__device__ __forceinline__ void mma16816(float* c, const uint32_t* a, const uint32_t* b) {
    asm volatile("mma.sync.aligned.m16n8k16.row.col.f32.bf16.bf16.f32 "
        "{%0,%1,%2,%3}, {%4,%5,%6,%7}, {%8,%9}, {%0,%1,%2,%3};"
        : "+f"(c[0]), "+f"(c[1]), "+f"(c[2]), "+f"(c[3])
        : "r"(a[0]), "r"(a[1]), "r"(a[2]), "r"(a[3]), "r"(b[0]), "r"(b[1]));
}
__device__ __forceinline__ void mma16832f8(float* c, const uint32_t* a, const uint32_t* b) {
    asm volatile("mma.sync.aligned.m16n8k32.row.col.f32.e4m3.e4m3.f32 "
        "{%0,%1,%2,%3}, {%4,%5,%6,%7}, {%8,%9}, {%0,%1,%2,%3};"
        : "+f"(c[0]), "+f"(c[1]), "+f"(c[2]), "+f"(c[3])
        : "r"(a[0]), "r"(a[1]), "r"(a[2]), "r"(a[3]), "r"(b[0]), "r"(b[1]));
}
__device__ __forceinline__ uint32_t pack_f8x4(float a, float b, float c, float d) {
    __nv_fp8x2_storage_t lo = __nv_cvt_float2_to_fp8x2(make_float2(a, b), __NV_SATFINITE, __NV_E4M3);
    __nv_fp8x2_storage_t hi = __nv_cvt_float2_to_fp8x2(make_float2(c, d), __NV_SATFINITE, __NV_E4M3);
    return (uint32_t)lo | ((uint32_t)hi << 16);
}

// ---------------- elementwise kernels ----------------
__global__ void f2bf(const float* __restrict__ in, __nv_bfloat16* __restrict__ out, int n) {
    int i = (blockIdx.x * 256 + threadIdx.x) * 4;
    if (i >= n) return;
    float4 v = *(const float4*)(in + i);
    __nv_bfloat162 p0 = __floats2bfloat162_rn(v.x, v.y);
    __nv_bfloat162 p1 = __floats2bfloat162_rn(v.z, v.w);
    *(uint2*)(out + i) = make_uint2(*(uint32_t*)&p0, *(uint32_t*)&p1);
}
__global__ void f2f8(const float* __restrict__ in, uint8_t* __restrict__ out, int n) {
    int i = (blockIdx.x * 256 + threadIdx.x) * 4;
    if (i >= n) return;
    float4 v = *(const float4*)(in + i);
    *(uint32_t*)(out + i) = pack_f8x4(v.x, v.y, v.z, v.w);
}

__global__ void build_x_mem(const float* __restrict__ inp, float* __restrict__ x,
                            __nv_bfloat16* __restrict__ mem, int r) {
    int d = threadIdx.x, n = blockIdx.x, b = blockIdx.y;
    long xi = ((long)b * NPTS + n) * DD + d;
    long mi = ((long)b * KPAD + n) * DD + d;
    if (n == 0) {
        float val = (r == 0) ? inp[xi] : x[xi];
        x[xi] = val;
        __nv_bfloat16 bv = __float2bfloat16(val);
        mem[mi] = bv;
        mem[((long)b * KPAD + NPTS + r) * DD + d] = bv;
    } else {
        float val = inp[xi];
        x[xi] = val;
        mem[mi] = __float2bfloat16(val);
    }
}

// warp-per-row LN, fp32 in -> bf16 out (norm1)
__global__ void ln_f32(const float* __restrict__ in, const float* __restrict__ w,
                       const float* __restrict__ b, __nv_bfloat16* __restrict__ out,
                       int rows, float scale) {
    int warp = threadIdx.x >> 5, lane = threadIdx.x & 31;
    int row = blockIdx.x * 8 + warp;
    if (row >= rows) return;
    const float* x = in + (long)row * DD;
    __nv_bfloat16* y = out + (long)row * DD;
    float4 v[3]; float s = 0.f;
    #pragma unroll
    for (int j = 0; j < 3; j++) {
        v[j] = *(const float4*)(x + lane * 4 + j * 128);
        s += (v[j].x + v[j].y) + (v[j].z + v[j].w);
    }
    #pragma unroll
    for (int o = 16; o; o >>= 1) s += __shfl_xor_sync(~0u, s, o);
    float mu = s * (1.f / 384.f), q = 0.f;
    #pragma unroll
    for (int j = 0; j < 3; j++) {
        v[j].x -= mu; v[j].y -= mu; v[j].z -= mu; v[j].w -= mu;
        q += v[j].x * v[j].x + v[j].y * v[j].y + v[j].z * v[j].z + v[j].w * v[j].w;
    }
    #pragma unroll
    for (int o = 16; o; o >>= 1) q += __shfl_xor_sync(~0u, q, o);
    float rs = rsqrtf(q * (1.f / 384.f) + 1e-6f);
    #pragma unroll
    for (int j = 0; j < 3; j++) {
        int c = lane * 4 + j * 128;
        float4 wv = *(const float4*)(w + c);
        float4 bv = *(const float4*)(b + c);
        __nv_bfloat162 p0 = __floats2bfloat162_rn((v[j].x * rs * wv.x + bv.x) * scale,
                                                  (v[j].y * rs * wv.y + bv.y) * scale);
        __nv_bfloat162 p1 = __floats2bfloat162_rn((v[j].z * rs * wv.z + bv.z) * scale,
                                                  (v[j].w * rs * wv.w + bv.w) * scale);
        *(uint2*)(y + c) = make_uint2(*(uint32_t*)&p0, *(uint32_t*)&p1);
    }
}

// warp-per-row LN, fp32 in -> FP8 out (norm2 -> fc1 input)
__global__ void ln_f32_f8(const float* __restrict__ in, const float* __restrict__ w,
                          const float* __restrict__ b, uint8_t* __restrict__ out, int rows) {
    int warp = threadIdx.x >> 5, lane = threadIdx.x & 31;
    int row = blockIdx.x * 8 + warp;
    if (row >= rows) return;
    const float* x = in + (long)row * DD;
    uint8_t* y = out + (long)row * DD;
    float4 v[3]; float s = 0.f;
    #pragma unroll
    for (int j = 0; j < 3; j++) {
        v[j] = *(const float4*)(x + lane * 4 + j * 128);
        s += (v[j].x + v[j].y) + (v[j].z + v[j].w);
    }
    #pragma unroll
    for (int o = 16; o; o >>= 1) s += __shfl_xor_sync(~0u, s, o);
    float mu = s * (1.f / 384.f), q = 0.f;
    #pragma unroll
    for (int j = 0; j < 3; j++) {
        v[j].x -= mu; v[j].y -= mu; v[j].z -= mu; v[j].w -= mu;
        q += v[j].x * v[j].x + v[j].y * v[j].y + v[j].z * v[j].z + v[j].w * v[j].w;
    }
    #pragma unroll
    for (int o = 16; o; o >>= 1) q += __shfl_xor_sync(~0u, q, o);
    float rs = rsqrtf(q * (1.f / 384.f) + 1e-6f);
    #pragma unroll
    for (int j = 0; j < 3; j++) {
        int c = lane * 4 + j * 128;
        float4 wv = *(const float4*)(w + c);
        float4 bv = *(const float4*)(b + c);
        *(uint32_t*)(y + c) = pack_f8x4(v[j].x * rs * wv.x + bv.x, v[j].y * rs * wv.y + bv.y,
                                        v[j].z * rs * wv.z + bv.z, v[j].w * rs * wv.w + bv.w);
    }
}

// LN body on bf16 row -> bf16 (device inline)
__device__ __forceinline__ void ln_row_b16(const __nv_bfloat16* __restrict__ x,
                                           const float* __restrict__ w,
                                           const float* __restrict__ b,
                                           __nv_bfloat16* __restrict__ y,
                                           int lane, float scale) {
    float4 v[3]; float s = 0.f;
    #pragma unroll
    for (int j = 0; j < 3; j++) {
        uint2 u = *(const uint2*)(x + lane * 4 + j * 128);
        __nv_bfloat162 h0 = *(__nv_bfloat162*)&u.x;
        __nv_bfloat162 h1 = *(__nv_bfloat162*)&u.y;
        v[j].x = __bfloat162float(h0.x); v[j].y = __bfloat162float(h0.y);
        v[j].z = __bfloat162float(h1.x); v[j].w = __bfloat162float(h1.y);
        s += (v[j].x + v[j].y) + (v[j].z + v[j].w);
    }
    #pragma unroll
    for (int o = 16; o; o >>= 1) s += __shfl_xor_sync(~0u, s, o);
    float mu = s * (1.f / 384.f), q = 0.f;
    #pragma unroll
    for (int j = 0; j < 3; j++) {
        v[j].x -= mu; v[j].y -= mu; v[j].z -= mu; v[j].w -= mu;
        q += v[j].x * v[j].x + v[j].y * v[j].y + v[j].z * v[j].z + v[j].w * v[j].w;
    }
    #pragma unroll
    for (int o = 16; o; o >>= 1) q += __shfl_xor_sync(~0u, q, o);
    float rs = rsqrtf(q * (1.f / 384.f) + 1e-6f);
    #pragma unroll
    for (int j = 0; j < 3; j++) {
        int c = lane * 4 + j * 128;
        float4 wv = *(const float4*)(w + c);
        float4 bv = *(const float4*)(b + c);
        __nv_bfloat162 p0 = __floats2bfloat162_rn((v[j].x * rs * wv.x + bv.x) * scale,
                                                  (v[j].y * rs * wv.y + bv.y) * scale);
        __nv_bfloat162 p1 = __floats2bfloat162_rn((v[j].z * rs * wv.z + bv.z) * scale,
                                                  (v[j].w * rs * wv.w + bv.w) * scale);
        *(uint2*)(y + c) = make_uint2(*(uint32_t*)&p0, *(uint32_t*)&p1);
    }
}

// an-LN: bf16 in -> FP8 out (proj input)
__global__ void ln_b16_f8(const __nv_bfloat16* __restrict__ in, const float* __restrict__ w,
                          const float* __restrict__ b, uint8_t* __restrict__ out,
                          int rows, long strIn, long strOut) {
    int warp = threadIdx.x >> 5, lane = threadIdx.x & 31;
    int row = blockIdx.x * 8 + warp;
    if (row >= rows) return;
    const __nv_bfloat16* x = in + (long)blockIdx.y * strIn + (long)row * DD;
    uint8_t* y = out + (long)blockIdx.y * strOut + (long)row * DD;
    float4 v[3]; float s = 0.f;
    #pragma unroll
    for (int j = 0; j < 3; j++) {
        uint2 u = *(const uint2*)(x + lane * 4 + j * 128);
        __nv_bfloat162 h0 = *(__nv_bfloat162*)&u.x;
        __nv_bfloat162 h1 = *(__nv_bfloat162*)&u.y;
        v[j].x = __bfloat162float(h0.x); v[j].y = __bfloat162float(h0.y);
        v[j].z = __bfloat162float(h1.x); v[j].w = __bfloat162float(h1.y);
        s += (v[j].x + v[j].y) + (v[j].z + v[j].w);
    }
    #pragma unroll
    for (int o = 16; o; o >>= 1) s += __shfl_xor_sync(~0u, s, o);
    float mu = s * (1.f / 384.f), q = 0.f;
    #pragma unroll
    for (int j = 0; j < 3; j++) {
        v[j].x -= mu; v[j].y -= mu; v[j].z -= mu; v[j].w -= mu;
        q += v[j].x * v[j].x + v[j].y * v[j].y + v[j].z * v[j].z + v[j].w * v[j].w;
    }
    #pragma unroll
    for (int o = 16; o; o >>= 1) q += __shfl_xor_sync(~0u, q, o);
    float rs = rsqrtf(q * (1.f / 384.f) + 1e-6f);
    #pragma unroll
    for (int j = 0; j < 3; j++) {
        int c = lane * 4 + j * 128;
        float4 wv = *(const float4*)(w + c);
        float4 bv = *(const float4*)(b + c);
        *(uint32_t*)(y + c) = pack_f8x4(v[j].x * rs * wv.x + bv.x, v[j].y * rs * wv.y + bv.y,
                                        v[j].z * rs * wv.z + bv.z, v[j].w * rs * wv.w + bv.w);
    }
}

// fused q-LN + k-LN in one launch (dispatcher)
__global__ void ln_qk(const __nv_bfloat16* __restrict__ bqr, const float* __restrict__ qw,
                      const float* __restrict__ qb, __nv_bfloat16* __restrict__ bq,
                      int Mq, float scale,
                      const __nv_bfloat16* __restrict__ bkr, const float* __restrict__ kw,
                      const float* __restrict__ kb, __nv_bfloat16* __restrict__ bk,
                      int curM, long mS, int nQ, int nKB) {
    int warp = threadIdx.x >> 5, lane = threadIdx.x & 31;
    int bid = blockIdx.x;
    if (bid < nQ) {
        int row = bid * 8 + warp;
        if (row >= Mq) return;
        ln_row_b16(bqr + (long)row * DD, qw, qb, bq + (long)row * DD, lane, scale);
    } else {
        int idx = bid - nQ;
        int bz = idx / nKB, blk = idx % nKB;
        int row = blk * 8 + warp;
        if (row >= curM) return;
        long off = (long)bz * mS + (long)row * DD;
        ln_row_b16(bkr + off, kw, kb, bk + off, lane, 1.f);
    }
}

// ---------------- GEMM common config ----------------
#define BM 128
#define BN 128
#define SROWB 80
#define STGB ((BM + BN) * SROWB)   // 20480
#define NSTAGE 3
#define SMEMB (NSTAGE * STGB)      // 61440

#define EPI_EXP   2
#define EPI_AVB   3
#define EPI_GELU  4
#define EPI_RES   5

// ---------------- bf16 GEMM (attention path) ----------------
template<int EPI>
__global__ void __launch_bounds__(256, 2)
mma_gemm(const __nv_bfloat16* __restrict__ A, const __nv_bfloat16* __restrict__ B,
         void* __restrict__ Cv,
         int M, int K, int lda, int ldb, int ldc, int curM,
         long strA, long strB, long strC)
{
    extern __shared__ __align__(16) char smem_[];
    __shared__ float rinv[BM];
    A += (long)blockIdx.z * strA;
    B += (long)blockIdx.z * strB;
    int m0 = blockIdx.y * BM, n0 = blockIdx.x * BN;
    int t = threadIdx.x;
    int warp = t >> 5, lane = t & 31;
    int wm = warp & 1, wn = warp >> 1;

    float acc[4][4][4];
    #pragma unroll
    for (int i = 0; i < 4; i++)
        #pragma unroll
        for (int j = 0; j < 4; j++)
            #pragma unroll
            for (int q = 0; q < 4; q++) acc[i][j][q] = 0.f;

    uint32_t sb = (uint32_t)__cvta_generic_to_shared(smem_);
    int sRow = t >> 2, sCol = (t & 3) * 16;
    auto stage = [&](int kt) {
        uint32_t tA = sb + (uint32_t)((kt % NSTAGE) * STGB);
        uint32_t tB = tA + BM * SROWB;
        int k0 = kt * 32;
        #pragma unroll
        for (int i2 = 0; i2 < 2; i2++) {
            int row = sRow + i2 * 64;
            int gm = m0 + row; gm = gm < M ? gm : M - 1;
            cpa16(tA + (uint32_t)(row * SROWB + sCol), A + (long)gm * lda + k0 + sCol / 2);
        }
        #pragma unroll
        for (int i2 = 0; i2 < 2; i2++) {
            int row = sRow + i2 * 64;
            cpa16(tB + (uint32_t)(row * SROWB + sCol), B + (long)(n0 + row) * ldb + k0 + sCol / 2);
        }
        cpa_commit();
    };

    const int T = K >> 5;
    stage(0); stage(1);

    uint32_t aOff = (uint32_t)((wm * 64 + (lane & 15)) * SROWB + (lane >> 4) * 16);
    uint32_t bOff = (uint32_t)(BM * SROWB + (wn * 32 + (lane & 7)) * SROWB + ((lane >> 3) & 1) * 16);

    float psum = 0.f;

    for (int i = 0; i < T; i++) {
        asm volatile("cp.async.wait_group 1;" ::: "memory");
        __syncthreads();
        if (EPI == EPI_AVB) {
            const __nv_bfloat16* arow = (const __nv_bfloat16*)
                (smem_ + (size_t)(i % NSTAGE) * STGB + (t >> 1) * SROWB + (t & 1) * 32);
            #pragma unroll
            for (int z = 0; z < 4; z++) {
                uint2 u = *(const uint2*)(arow + z * 4);
                __nv_bfloat162 a0 = *(__nv_bfloat162*)&u.x;
                __nv_bfloat162 a1 = *(__nv_bfloat162*)&u.y;
                psum += (__bfloat162float(a0.x) + __bfloat162float(a0.y))
                      + (__bfloat162float(a1.x) + __bfloat162float(a1.y));
            }
        }
        if (i + 2 < T) stage(i + 2);
        else cpa_commit();
        uint32_t tbase = sb + (uint32_t)((i % NSTAGE) * STGB);
        #pragma unroll
        for (int kk = 0; kk < 2; kk++) {
            uint32_t af[4][4], bf_[4][2];
            #pragma unroll
            for (int mt = 0; mt < 4; mt++)
                ldm4(af[mt], tbase + aOff + (uint32_t)(mt * 16 * SROWB + kk * 32));
            #pragma unroll
            for (int nt = 0; nt < 4; nt++)
                ldm2(bf_[nt], tbase + bOff + (uint32_t)(nt * 8 * SROWB + kk * 32));
            #pragma unroll
            for (int mt = 0; mt < 4; mt++)
                #pragma unroll
                for (int nt = 0; nt < 4; nt++)
                    mma16816(acc[mt][nt], af[mt], bf_[nt]);
        }
    }
    __syncthreads();

    if (EPI == EPI_AVB) {
        psum += __shfl_xor_sync(~0u, psum, 1);
        if ((t & 1) == 0) rinv[t >> 1] = 1.f / psum;
        __syncthreads();
    }

    int g = lane >> 2, tg = lane & 3;
    #pragma unroll
    for (int mt = 0; mt < 4; mt++) {
        #pragma unroll
        for (int nt = 0; nt < 4; nt++) {
            int gm = m0 + wm * 64 + mt * 16 + g;
            int gn = n0 + wn * 32 + nt * 8 + tg * 2;
            float* cc = acc[mt][nt];
            #pragma unroll
            for (int h = 0; h < 2; h++) {
                int gmh = gm + h * 8;
                if (gmh >= M) continue;
                float v0 = cc[h * 2 + 0], v1 = cc[h * 2 + 1];
                if (EPI == EPI_EXP) {
                    __nv_bfloat16* C = (__nv_bfloat16*)Cv + (long)blockIdx.z * strC;
                    float e0 = (gn < curM)     ? __expf(v0) : 0.f;
                    float e1 = (gn + 1 < curM) ? __expf(v1) : 0.f;
                    __nv_bfloat162 p = __floats2bfloat162_rn(e0, e1);
                    *(uint32_t*)&C[(long)gmh * ldc + gn] = *(uint32_t*)&p;
                } else {   // EPI_AVB
                    __nv_bfloat16* C = (__nv_bfloat16*)Cv + (long)blockIdx.z * strC;
                    float inv = rinv[gmh - m0];
                    __nv_bfloat162 p = __floats2bfloat162_rn(v0 * inv, v1 * inv);
                    *(uint32_t*)&C[(long)gmh * ldc + gn] = *(uint32_t*)&p;
                }
            }
        }
    }
}

// ---------------- FP8 GEMM (proj / fc1 / fc2): same tile geometry, k64/iter ----------------
template<int EPI>
__global__ void __launch_bounds__(256, 2)
mma_f8(const uint8_t* __restrict__ A, const uint8_t* __restrict__ B,
       const float* __restrict__ bias, const float* __restrict__ ls,
       void* __restrict__ Cv, int M, int K, int lda, int ldb, int ldc)
{
    extern __shared__ __align__(16) char smem_[];
    int m0 = blockIdx.y * BM, n0 = blockIdx.x * BN;
    int t = threadIdx.x;
    int warp = t >> 5, lane = t & 31;
    int wm = warp & 1, wn = warp >> 1;

    float acc[4][4][4];
    #pragma unroll
    for (int i = 0; i < 4; i++)
        #pragma unroll
        for (int j = 0; j < 4; j++)
            #pragma unroll
            for (int q = 0; q < 4; q++) acc[i][j][q] = 0.f;

    uint32_t sb = (uint32_t)__cvta_generic_to_shared(smem_);
    int sRow = t >> 2, sCol = (t & 3) * 16;
    auto stage = [&](int kt) {
        uint32_t tA = sb + (uint32_t)((kt % NSTAGE) * STGB);
        uint32_t tB = tA + BM * SROWB;
        int k0 = kt * 64;                         // 64 fp8 per 64-byte row
        #pragma unroll
        for (int i2 = 0; i2 < 2; i2++) {
            int row = sRow + i2 * 64;
            int gm = m0 + row; gm = gm < M ? gm : M - 1;
            cpa16(tA + (uint32_t)(row * SROWB + sCol), A + (long)gm * lda + k0 + sCol);
        }
        #pragma unroll
        for (int i2 = 0; i2 < 2; i2++) {
            int row = sRow + i2 * 64;
            cpa16(tB + (uint32_t)(row * SROWB + sCol), B + (long)(n0 + row) * ldb + k0 + sCol);
        }
        cpa_commit();
    };

    const int T = K >> 6;
    stage(0); stage(1);

    uint32_t aOff = (uint32_t)((wm * 64 + (lane & 15)) * SROWB + (lane >> 4) * 16);
    uint32_t bOff = (uint32_t)(BM * SROWB + (wn * 32 + (lane & 7)) * SROWB + ((lane >> 3) & 1) * 16);

    for (int i = 0; i < T; i++) {
        asm volatile("cp.async.wait_group 1;" ::: "memory");
        __syncthreads();
        if (i + 2 < T) stage(i + 2);
        else cpa_commit();
        uint32_t tbase = sb + (uint32_t)((i % NSTAGE) * STGB);
        #pragma unroll
        for (int kk = 0; kk < 2; kk++) {          // each kk = 32 bytes = k32 fp8
            uint32_t af[4][4], bf_[4][2];
            #pragma unroll
            for (int mt = 0; mt < 4; mt++)
                ldm4(af[mt], tbase + aOff + (uint32_t)(mt * 16 * SROWB + kk * 32));
            #pragma unroll
            for (int nt = 0; nt < 4; nt++)
                ldm2(bf_[nt], tbase + bOff + (uint32_t)(nt * 8 * SROWB + kk * 32));
            #pragma unroll
            for (int mt = 0; mt < 4; mt++)
                #pragma unroll
                for (int nt = 0; nt < 4; nt++)
                    mma16832f8(acc[mt][nt], af[mt], bf_[nt]);
        }
    }
    __syncthreads();

    int g = lane >> 2, tg = lane & 3;
    #pragma unroll
    for (int mt = 0; mt < 4; mt++) {
        #pragma unroll
        for (int nt = 0; nt < 4; nt++) {
            int gm = m0 + wm * 64 + mt * 16 + g;
            int gn = n0 + wn * 32 + nt * 8 + tg * 2;
            float* cc = acc[mt][nt];
            float2 bv = *(const float2*)&bias[gn];
            float b0 = bv.x, b1 = bv.y, l0 = 0.f, l1 = 0.f;
            if (EPI == EPI_RES) { float2 lv = *(const float2*)&ls[gn]; l0 = lv.x; l1 = lv.y; }
            #pragma unroll
            for (int h = 0; h < 2; h++) {
                int gmh = gm + h * 8;
                if (gmh >= M) continue;
                float v0 = cc[h * 2 + 0], v1 = cc[h * 2 + 1];
                if (EPI == EPI_RES) {
                    float* C = (float*)Cv;
                    long ci = (long)gmh * ldc + gn;
                    float2 old = *(float2*)&C[ci];
                    *(float2*)&C[ci] = make_float2((v0 + b0) * l0 + old.x,
                                                   (v1 + b1) * l1 + old.y);
                } else {   // EPI_GELU -> fp8 out
                    uint8_t* C = (uint8_t*)Cv;
                    v0 += b0; v1 += b1;
                    v0 = 0.5f * v0 * (1.f + erff(v0 * 0.70710678118654752f));
                    v1 = 0.5f * v1 * (1.f + erff(v1 * 0.70710678118654752f));
                    __nv_fp8x2_storage_t p = __nv_cvt_float2_to_fp8x2(make_float2(v0, v1),
                                                                      __NV_SATFINITE, __NV_E4M3);
                    *(uint16_t*)&C[(long)gmh * ldc + gn] = (uint16_t)p;
                }
            }
        }
    }
}

// ---------------- fused QB + KV GEMM (bf16, dispatcher, K=384) ----------------
__global__ void __launch_bounds__(256, 2)
mma_qkv(const __nv_bfloat16* __restrict__ Axn, const __nv_bfloat16* __restrict__ Wq,
        const float* __restrict__ biasq,
        const __nv_bfloat16* __restrict__ Amem, const __nv_bfloat16* __restrict__ Wkv,
        const float* __restrict__ biaskv,
        __nv_bfloat16* __restrict__ Cq, __nv_bfloat16* __restrict__ Ck,
        __nv_bfloat16* __restrict__ Cvt,
        int Mq, int curM, int nQB, long mS, long vtS)
{
    extern __shared__ __align__(16) char smem_[];
    int bid = blockIdx.x;
    bool isQ = bid < nQB;
    const __nv_bfloat16 *A, *B;
    const float* bias;
    int M, m0, n0;
    long zC = 0;
    if (isQ) {
        int bx = bid % 3, by = bid / 3;
        A = Axn; B = Wq; bias = biasq; M = Mq;
        m0 = by * BM; n0 = bx * BN;
    } else {
        int idx = bid - nQB;
        int bx = idx % 6, by = (idx / 6) % 5;
        zC = idx / 30;
        A = Amem + zC * mS; B = Wkv; bias = biaskv; M = curM;
        m0 = by * BM; n0 = bx * BN;
    }
    int t = threadIdx.x;
    int warp = t >> 5, lane = t & 31;
    int wm = warp & 1, wn = warp >> 1;

    float acc[4][4][4];
    #pragma unroll
    for (int i = 0; i < 4; i++)
        #pragma unroll
        for (int j = 0; j < 4; j++)
            #pragma unroll
            for (int q = 0; q < 4; q++) acc[i][j][q] = 0.f;

    uint32_t sb = (uint32_t)__cvta_generic_to_shared(smem_);
    int sRow = t >> 2, sCol = (t & 3) * 16;
    auto stage = [&](int kt) {
        uint32_t tA = sb + (uint32_t)((kt % NSTAGE) * STGB);
        uint32_t tB = tA + BM * SROWB;
        int k0 = kt * 32;
        #pragma unroll
        for (int i2 = 0; i2 < 2; i2++) {
            int row = sRow + i2 * 64;
            int gm = m0 + row; gm = gm < M ? gm : M - 1;
            cpa16(tA + (uint32_t)(row * SROWB + sCol), A + (long)gm * DD + k0 + sCol / 2);
        }
        #pragma unroll
        for (int i2 = 0; i2 < 2; i2++) {
            int row = sRow + i2 * 64;
            cpa16(tB + (uint32_t)(row * SROWB + sCol), B + (long)(n0 + row) * DD + k0 + sCol / 2);
        }
        cpa_commit();
    };

    const int T = DD >> 5;    // 12
    stage(0); stage(1);

    uint32_t aOff = (uint32_t)((wm * 64 + (lane & 15)) * SROWB + (lane >> 4) * 16);
    uint32_t bOff = (uint32_t)(BM * SROWB + (wn * 32 + (lane & 7)) * SROWB + ((lane >> 3) & 1) * 16);

    for (int i = 0; i < T; i++) {
        asm volatile("cp.async.wait_group 1;" ::: "memory");
        __syncthreads();
        if (i + 2 < T) stage(i + 2);
        else cpa_commit();
        uint32_t tbase = sb + (uint32_t)((i % NSTAGE) * STGB);
        #pragma unroll
        for (int kk = 0; kk < 2; kk++) {
            uint32_t af[4][4], bf_[4][2];
            #pragma unroll
            for (int mt = 0; mt < 4; mt++)
                ldm4(af[mt], tbase + aOff + (uint32_t)(mt * 16 * SROWB + kk * 32));
            #pragma unroll
            for (int nt = 0; nt < 4; nt++)
                ldm2(bf_[nt], tbase + bOff + (uint32_t)(nt * 8 * SROWB + kk * 32));
            #pragma unroll
            for (int mt = 0; mt < 4; mt++)
                #pragma unroll
                for (int nt = 0; nt < 4; nt++)
                    mma16816(acc[mt][nt], af[mt], bf_[nt]);
        }
    }
    __syncthreads();

    int g = lane >> 2, tg = lane & 3;
    #pragma unroll
    for (int mt = 0; mt < 4; mt++) {
        #pragma unroll
        for (int nt = 0; nt < 4; nt++) {
            int gm = m0 + wm * 64 + mt * 16 + g;
            int gn = n0 + wn * 32 + nt * 8 + tg * 2;
            float* cc = acc[mt][nt];
            float2 bv = *(const float2*)&bias[gn];
            float b0 = bv.x, b1 = bv.y;
            #pragma unroll
            for (int h = 0; h < 2; h++) {
                int gmh = gm + h * 8;
                if (gmh >= M) continue;
                float v0 = cc[h * 2 + 0] + b0, v1 = cc[h * 2 + 1] + b1;
                if (isQ) {
                    __nv_bfloat162 p = __floats2bfloat162_rn(v0, v1);
                    *(uint32_t*)&Cq[(long)gmh * DD + gn] = *(uint32_t*)&p;
                } else if (gn < DD) {
                    __nv_bfloat16* C = Ck + zC * mS;
                    __nv_bfloat162 p = __floats2bfloat162_rn(v0, v1);
                    *(uint32_t*)&C[(long)gmh * DD + gn] = *(uint32_t*)&p;
                } else {
                    __nv_bfloat16* C2 = Cvt + zC * vtS;
                    int vn = gn - DD;
                    C2[(long)vn * KPAD + gmh]       = __float2bfloat16(v0);
                    C2[(long)(vn + 1) * KPAD + gmh] = __float2bfloat16(v1);
                }
            }
        }
    }
}

// ---------------- host ----------------
extern "C" void kernel_launch(void* const* d_in, const int* in_sizes, int n_in,
                              void* d_out, int out_size)
{
    const float* x_in = (const float*)d_in[0];
    const float* n1w = (const float*)d_in[1];  const float* n1b = (const float*)d_in[2];
    const float* qkvw = (const float*)d_in[3]; const float* qkvb = (const float*)d_in[4];
    const float* qnw = (const float*)d_in[5];  const float* qnb = (const float*)d_in[6];
    const float* knw = (const float*)d_in[7];  const float* knb = (const float*)d_in[8];
    const float* anw = (const float*)d_in[9];  const float* anb = (const float*)d_in[10];
    const float* projw = (const float*)d_in[11]; const float* projb = (const float*)d_in[12];
    const float* ls1 = (const float*)d_in[13];
    const float* n2w = (const float*)d_in[14]; const float* n2b = (const float*)d_in[15];
    const float* fc1w = (const float*)d_in[16]; const float* fc1b = (const float*)d_in[17];
    const float* fc2w = (const float*)d_in[18]; const float* fc2b = (const float*)d_in[19];
    const float* ls2 = (const float*)d_in[20];

    float *gx;
    __nv_bfloat16 *bxn, *bq, *bqr, *bk, *bkr, *bmem, *bvt, *battn, *bavr, *wq;
    uint8_t *fxn, *ftmp, *fh, *w8p, *w81, *w82;
    cudaGetSymbolAddress((void**)&gx, g_x);
    cudaGetSymbolAddress((void**)&bxn, b_xn);   cudaGetSymbolAddress((void**)&bq, b_q);
    cudaGetSymbolAddress((void**)&bqr, b_qraw); cudaGetSymbolAddress((void**)&bk, b_k);
    cudaGetSymbolAddress((void**)&bkr, b_kraw); cudaGetSymbolAddress((void**)&bmem, b_mem);
    cudaGetSymbolAddress((void**)&bvt, b_vt);   cudaGetSymbolAddress((void**)&battn, b_attn);
    cudaGetSymbolAddress((void**)&bavr, b_avraw);
    cudaGetSymbolAddress((void**)&wq, w_qkv);
    cudaGetSymbolAddress((void**)&fxn, f8_xn);  cudaGetSymbolAddress((void**)&ftmp, f8_tmp);
    cudaGetSymbolAddress((void**)&fh, f8_h);
    cudaGetSymbolAddress((void**)&w8p, w8_p);   cudaGetSymbolAddress((void**)&w81, w8_1);
    cudaGetSymbolAddress((void**)&w82, w8_2);

    cudaFuncSetAttribute(mma_qkv,            cudaFuncAttributeMaxDynamicSharedMemorySize, SMEMB);
    cudaFuncSetAttribute(mma_gemm<EPI_EXP>,  cudaFuncAttributeMaxDynamicSharedMemorySize, SMEMB);
    cudaFuncSetAttribute(mma_gemm<EPI_AVB>,  cudaFuncAttributeMaxDynamicSharedMemorySize, SMEMB);
    cudaFuncSetAttribute(mma_f8<EPI_GELU>,   cudaFuncAttributeMaxDynamicSharedMemorySize, SMEMB);
    cudaFuncSetAttribute(mma_f8<EPI_RES>,    cudaFuncAttributeMaxDynamicSharedMemorySize, SMEMB);

    int n;
    n = LL * 3 * DD * DD; f2bf<<<(n / 4 + 255) / 256, 256>>>(qkvw, wq, n);
    n = LL * DD * DD;     f2f8<<<(n / 4 + 255) / 256, 256>>>(projw, w8p, n);
    n = LL * HH * DD;     f2f8<<<(n / 4 + 255) / 256, 256>>>(fc1w, w81, n);
    n = LL * DD * HH;     f2f8<<<(n / 4 + 255) / 256, 256>>>(fc2w, w82, n);

    const float scale = 1.0f / sqrtf((float)DD);
    const long xS = (long)NPTS * DD, mS = (long)KPAD * DD;
    const long vtS = (long)DD * KPAD, aS = (long)NPTS * KPAD;
    const int Mflat = BB * NPTS;                 // 18464
    const int KAV = 608;
    const int nQB = 3 * 145;                      // 435 q-tiles
    const int nKV = 6 * 5 * BB;                   // 960 kv-tiles
    const dim3 gFlatD(3, 145, 1), gFlatH(12, 145, 1);

    for (int r = 0; r < 4; r++) {
        int curM = NPTS + r;
        int nKB = (curM + 7) / 8;
        build_x_mem<<<dim3(NPTS, BB), DD>>>(x_in, gx, bmem, r);
        for (int l = 0; l < LL; l++) {
            const __nv_bfloat16* Wq = wq + (long)l * 3 * DD * DD;
            const __nv_bfloat16* Wkv = Wq + (long)DD * DD;
            const float* bqp = qkvb + (long)l * 3 * DD;
            const float* bkvp = bqp + DD;

            // xn = LN(x, norm1) -> bf16
            ln_f32<<<(Mflat + 7) / 8, 256>>>(gx, n1w + l * DD, n1b + l * DD, bxn, Mflat, 1.f);
            // fused: q = xn@Wq^T+bq  AND  [k|v] = mem@Wkv^T+bkv
            mma_qkv<<<nQB + nKV, 256, SMEMB>>>(bxn, Wq, bqp, bmem, Wkv, bkvp,
                bqr, bkr, bvt, Mflat, curM, nQB, mS, vtS);
            // fused q-LN (scale folded) + k-LN
            ln_qk<<<2308 + nKB * BB, 256>>>(bqr, qnw + l * DD, qnb + l * DD, bq,
                Mflat, scale, bkr, knw + l * DD, knb + l * DD, bk, curM, mS, 2308, nKB);
            // probs = exp(q_scaled @ k^T), masked -> bf16 (unnormalized)
            dim3 gLog(5, 5, BB);
            mma_gemm<EPI_EXP><<<gLog, 256, SMEMB>>>(bq, bk, battn,
                NPTS, DD, DD, DD, KPAD, curM, xS, mS, aS);
            // prod = (probs @ vT^T) / rowsum(probs) -> bf16
            dim3 gProd(3, 5, BB);
            mma_gemm<EPI_AVB><<<gProd, 256, SMEMB>>>(battn, bvt, bavr,
                NPTS, KAV, KPAD, KPAD, DD, 0, aS, vtS, xS);
            // an-LN -> FP8
            ln_b16_f8<<<dim3((NPTS + 7) / 8, 1, BB), 256>>>(bavr, anw + l * DD, anb + l * DD,
                ftmp, NPTS, xS, xS);
            // x += (prodn @ proj^T + pb) * ls1     [FP8]
            mma_f8<EPI_RES><<<gFlatD, 256, SMEMB>>>(ftmp, w8p + (long)l * DD * DD,
                projb + l * DD, ls1 + l * DD, gx, Mflat, DD, DD, DD, DD);
            // norm2 -> FP8
            ln_f32_f8<<<(Mflat + 7) / 8, 256>>>(gx, n2w + l * DD, n2b + l * DD, fxn, Mflat);
            // h = gelu(xn @ fc1^T + b1) -> FP8     [FP8]
            mma_f8<EPI_GELU><<<gFlatH, 256, SMEMB>>>(fxn, w81 + (long)l * HH * DD,
                fc1b + (long)l * HH, nullptr, fh, Mflat, DD, DD, DD, HH);
            // x += (h @ fc2^T + b2) * ls2          [FP8]
            mma_f8<EPI_RES><<<gFlatD, 256, SMEMB>>>(fh, w82 + (long)l * DD * HH,
                fc2b + l * DD, ls2 + l * DD, gx, Mflat, HH, HH, HH, DD);
        }
    }
    cudaMemcpyAsync(d_out, gx, (size_t)BB * NPTS * DD * sizeof(float),
                    cudaMemcpyDeviceToDevice);
}